// round 13
// baseline (speedup 1.0000x reference)
#include <cuda_runtime.h>
#include <cuda_fp16.h>
#include <math.h>
#include <stdint.h>

// ---------------- problem constants ----------------
#define Sq   2048
#define Dm   2048
#define Hn   16
#define KVn  4
#define DHd  128
#define En   8
#define Id   1024
#define HD   2048
#define KVD  512
#define EPSf 1e-6f

// ---------------- static device scratch ----------------
__device__ float g_q   [2*Sq*HD];    // two K-split partials
__device__ float g_k   [2*Sq*KVD];
__device__ float g_v   [2*Sq*KVD];
__device__ float g_t   [Sq*Dm];
__device__ float g_moe [2*Sq*Dm];
__device__ int   g_cnt [En];
__device__ int   g_ptok[En*Sq];
__device__ float g_pw  [En*Sq];
__device__ int   g_pslot[En*Sq];
// fp16 activations
__device__ __half g_hh [Sq*Dm];
__device__ __half g_hl [Sq*Dm];
__device__ __half g_qh [Sq*HD];
__device__ __half g_ql [Sq*HD];
__device__ __half g_kh2[Sq*KVD];
__device__ __half g_kl2[Sq*KVD];
__device__ __half g_vh [Sq*KVD];
__device__ __half g_vl [Sq*KVD];
__device__ __half g_oh [Sq*HD];
__device__ __half g_ol [Sq*HD];
__device__ __half g_th [Sq*Dm];
__device__ __half g_gateh[En*Sq*Id];
__device__ __half g_uph  [En*Sq*Id];
__device__ __half g_acth [En*Sq*Id];
// fp16 weights (qkv concatenated: cols 0-2047 q, 2048-2559 k, 2560-3071 v)
__device__ __half w_qkvh[Dm*3072];
__device__ __half w_qkvl[Dm*3072];
__device__ __half w_oh[HD*Dm];
__device__ __half w_ol[HD*Dm];
__device__ __half w_guh[En*Dm*2048];   // cols 0-1023 gate, 1024-2047 up
__device__ __half w_dh [En*Id*Dm];

// ---------------- helpers ----------------
__device__ __forceinline__ uint32_t smem_u32(const void* p) {
    uint32_t a;
    asm("{ .reg .u64 t; cvta.to.shared.u64 t, %1; cvt.u32.u64 %0, t; }" : "=r"(a) : "l"(p));
    return a;
}
__device__ __forceinline__ void ldsm4(uint32_t* r, uint32_t a) {
    asm volatile("ldmatrix.sync.aligned.m8n8.x4.shared.b16 {%0,%1,%2,%3}, [%4];"
                 : "=r"(r[0]), "=r"(r[1]), "=r"(r[2]), "=r"(r[3]) : "r"(a));
}
__device__ __forceinline__ void ldsm4t(uint32_t* r, uint32_t a) {
    asm volatile("ldmatrix.sync.aligned.m8n8.x4.trans.shared.b16 {%0,%1,%2,%3}, [%4];"
                 : "=r"(r[0]), "=r"(r[1]), "=r"(r[2]), "=r"(r[3]) : "r"(a));
}
__device__ __forceinline__ void mma16816(float* d, const uint32_t* a, const uint32_t* b) {
    asm volatile("mma.sync.aligned.m16n8k16.row.col.f32.f16.f16.f32 "
                 "{%0,%1,%2,%3}, {%4,%5,%6,%7}, {%8,%9}, {%0,%1,%2,%3};"
                 : "+f"(d[0]), "+f"(d[1]), "+f"(d[2]), "+f"(d[3])
                 : "r"(a[0]), "r"(a[1]), "r"(a[2]), "r"(a[3]), "r"(b[0]), "r"(b[1]));
}
__device__ __forceinline__ void split2(float x, float y, half2& hi, half2& lo) {
    hi = __floats2half2_rn(x, y);
    lo = __floats2half2_rn(x - __low2float(hi), y - __high2float(hi));
}
#define CP16(dst, src) \
    asm volatile("cp.async.cg.shared.global [%0], [%1], 16;" :: "r"((uint32_t)(dst)), "l"(src))
#define CP_COMMIT() asm volatile("cp.async.commit_group;" ::: "memory")
#define CP_WAIT(n)  asm volatile("cp.async.wait_group %0;" :: "n"(n) : "memory")

// ---------------- fused weight converts ----------------
__global__ __launch_bounds__(256) void conv_split_all(
    const float* wq, const float* wk, const float* wv, const float* wo,
    __half* qkvh, __half* qkvl, __half* woh, __half* wol)
{
    int y = blockIdx.y;
    int nblk = (y == 0 || y == 3) ? 2048 : 512;
    if (blockIdx.x >= nblk) return;
    const float* s = y == 0 ? wq : y == 1 ? wk : y == 2 ? wv : wo;
    size_t base = ((size_t)blockIdx.x * 256 + threadIdx.x) * 8;
#pragma unroll
    for (int j = 0; j < 2; j++) {
        size_t i = base + 4 * j;
        float4 v = *(const float4*)(s + i);
        half2 a0, b0, a1, b1;
        split2(v.x, v.y, a0, b0); split2(v.z, v.w, a1, b1);
        size_t d;
        __half *hi, *lo;
        if (y == 3) { d = i; hi = woh; lo = wol; }
        else if (y == 0) { size_t r = i >> 11, c = i & 2047; d = r * 3072 + c; hi = qkvh; lo = qkvl; }
        else { size_t r = i / 512, c = i % 512; d = r * 3072 + (y == 1 ? 2048 : 2560) + c; hi = qkvh; lo = qkvl; }
        *(half2*)(hi + d) = a0; *(half2*)(hi + d + 2) = a1;
        *(half2*)(lo + d) = b0; *(half2*)(lo + d + 2) = b1;
    }
}
__global__ __launch_bounds__(256) void conv_single_all(
    const float* wg, const float* wu, const float* wd,
    __half* guh, __half* wdh)
{
    int y = blockIdx.y;
    const float* s = y == 0 ? wg : y == 1 ? wu : wd;
    size_t base = ((size_t)blockIdx.x * 256 + threadIdx.x) * 16;
#pragma unroll
    for (int j = 0; j < 4; j++) {
        size_t i = base + 4 * j;
        float4 v = *(const float4*)(s + i);
        half2 h0 = __floats2half2_rn(v.x, v.y);
        half2 h1 = __floats2half2_rn(v.z, v.w);
        size_t d;
        __half* dst;
        if (y == 2) { d = i; dst = wdh; }
        else {
            size_t e = i / ((size_t)Dm * Id);
            size_t rem = i % ((size_t)Dm * Id);
            size_t r = rem >> 10, c = rem & 1023;
            d = e * (size_t)Dm * 2048 + r * 2048 + (y ? 1024 : 0) + c;
            dst = guh;
        }
        *(half2*)(dst + d) = h0; *(half2*)(dst + d + 2) = h1;
    }
}

// ================= fp16 mma GEMM, multi-stage cp.async pipeline =================
#define AT_SZ 10240     // 128 rows x 80B
#define BT_SZ 8704      // 32 rows x 272B
#define SM_SPLIT  (3 * (2*AT_SZ + 2*BT_SZ))          // 113664, no header
#define SM_SINGLE (2048 + 4 * (AT_SZ + BT_SZ))       // 77824, with header

// OMODE: 0 f32, 1 f32+res, 4 moe-scatter, 5 qkv triple (K-split partials), 6 gate/up pair
template<bool GATHER, bool EXPERT, bool SPLIT, int OMODE, int KSPLIT>
__global__ __launch_bounds__(256, 2) void gemm_mma2(
    const __half* __restrict__ Ah, const __half* __restrict__ Al,
    const __half* __restrict__ Bh, const __half* __restrict__ Bl,
    void* __restrict__ O0, void* __restrict__ O1,
    void* __restrict__ O2, void* __restrict__ O3,
    const float* __restrict__ res,
    int M, int N, int K)
{
    extern __shared__ char smem[];
    constexpr int STAGES = SPLIT ? 3 : 4;
    constexpr bool HDR = (GATHER || OMODE == 4);
    const int tid = threadIdx.x, lane = tid & 31, wid = tid >> 5;
    const int wm = wid & 3, wn = wid >> 2;
    const int STG  = SPLIT ? (2 * AT_SZ + 2 * BT_SZ) : (AT_SZ + BT_SZ);
    const int BOFF = SPLIT ? 2 * AT_SZ : AT_SZ;

    int e = 0, cnt = M;
    const __half* Ahe = Ah;
    const __half* Bhe = Bh;
    const __half* Ble = Bl;
    const int kz = (KSPLIT == 2) ? blockIdx.z : 0;
    const int Keff = K / KSPLIT;
    const int kbase = kz * Keff;
    if (EXPERT) {
        e = blockIdx.z;
        cnt = g_cnt[e];
        Bhe = Bh + (size_t)e * K * N;
        if (SPLIT) Ble = Bl + (size_t)e * K * N;
        if (!GATHER) Ahe = Ah + (size_t)e * Sq * K;
    }
    const int m0 = blockIdx.y * 128;
    if (EXPERT && m0 >= cnt) return;
    const int n0 = blockIdx.x * 128;

    int*   stok = (int*)smem;
    float* swt  = (float*)(smem + 512);
    int*   ssl  = (int*)(smem + 1024);
    if (HDR) {
        if (tid < 128) {
            int r = m0 + tid;
            bool ok = r < cnt;
            stok[tid] = ok ? g_ptok[e * Sq + r] : 0;
            if (OMODE == 4) {
                swt[tid] = ok ? g_pw[e * Sq + r] : 0.f;
                ssl[tid] = ok ? g_pslot[e * Sq + r] : 0;
            }
        }
        __syncthreads();
    }
    const uint32_t sb = smem_u32(smem);
    const uint32_t tb = sb + (HDR ? 2048 : 0);
    const int T = Keff / 32;

#define ISSUE(it) do { \
        int _k0 = kbase + (it) * 32; \
        uint32_t _s0 = tb + (uint32_t)((it) % STAGES) * STG; \
        _Pragma("unroll") \
        for (int _j = 0; _j < 2; _j++) { \
            int _idx = tid + _j * 256; \
            int _row = _idx >> 2, _c = _idx & 3; \
            int _gr = GATHER ? stok[_row] : (m0 + _row); \
            CP16(_s0 + _row * 80 + _c * 16, Ahe + (size_t)_gr * K + _k0 + _c * 8); \
            if (SPLIT) CP16(_s0 + AT_SZ + _row * 80 + _c * 16, Al + (size_t)_gr * K + _k0 + _c * 8); \
        } \
        _Pragma("unroll") \
        for (int _j = 0; _j < 2; _j++) { \
            int _idx = tid + _j * 256; \
            int _row = _idx >> 4, _c = _idx & 15; \
            CP16(_s0 + BOFF + _row * 272 + _c * 16, Bhe + (size_t)(_k0 + _row) * N + n0 + _c * 8); \
            if (SPLIT) CP16(_s0 + BOFF + BT_SZ + _row * 272 + _c * 16, \
                            Ble + (size_t)(_k0 + _row) * N + n0 + _c * 8); \
        } \
        CP_COMMIT(); \
    } while (0)

#pragma unroll
    for (int p = 0; p < STAGES - 1; p++) {
        if (p < T) ISSUE(p); else CP_COMMIT();
    }

    float acc[2][8][4] = {};
    for (int it = 0; it < T; ++it) {
        CP_WAIT(STAGES - 2);
        __syncthreads();
        {
            int nx = it + STAGES - 1;
            if (nx < T) ISSUE(nx); else CP_COMMIT();
        }
        uint32_t s0 = tb + (uint32_t)(it % STAGES) * STG;
#pragma unroll
        for (int ks = 0; ks < 2; ks++) {
            uint32_t ah[2][4], al[2][4], bh[8][2], bl[8][2];
            int am = wm * 32 + (lane & 7) + ((lane >> 3) & 1) * 8;
            int ak = ks * 16 + (lane >> 4) * 8;
            uint32_t ab = s0 + am * 80 + ak * 2;
            ldsm4(ah[0], ab);
            ldsm4(ah[1], ab + 16 * 80);
            if (SPLIT) { ldsm4(al[0], ab + AT_SZ); ldsm4(al[1], ab + AT_SZ + 16 * 80); }
            int bk = ks * 16 + (lane & 7) + ((lane >> 3) & 1) * 8;
            int bn = wn * 64 + (lane >> 4) * 8;
            uint32_t bb = s0 + BOFF + bk * 272 + bn * 2;
#pragma unroll
            for (int t = 0; t < 4; t++) {
                uint32_t rr[4];
                ldsm4t(rr, bb + t * 32);
                bh[2 * t][0] = rr[0]; bh[2 * t][1] = rr[1];
                bh[2 * t + 1][0] = rr[2]; bh[2 * t + 1][1] = rr[3];
                if (SPLIT) {
                    ldsm4t(rr, bb + BT_SZ + t * 32);
                    bl[2 * t][0] = rr[0]; bl[2 * t][1] = rr[1];
                    bl[2 * t + 1][0] = rr[2]; bl[2 * t + 1][1] = rr[3];
                }
            }
            // pass 1: hh products (16 independent MMAs)
#pragma unroll
            for (int mt = 0; mt < 2; mt++)
#pragma unroll
                for (int nt = 0; nt < 8; nt++)
                    mma16816(acc[mt][nt], ah[mt], bh[nt]);
            if (SPLIT) {
                // pass 2: hl products
#pragma unroll
                for (int mt = 0; mt < 2; mt++)
#pragma unroll
                    for (int nt = 0; nt < 8; nt++)
                        mma16816(acc[mt][nt], ah[mt], bl[nt]);
                // pass 3: lh products
#pragma unroll
                for (int mt = 0; mt < 2; mt++)
#pragma unroll
                    for (int nt = 0; nt < 8; nt++)
                        mma16816(acc[mt][nt], al[mt], bh[nt]);
            }
        }
    }
#undef ISSUE

    const int g = lane >> 2, tig = lane & 3;
#pragma unroll
    for (int mt = 0; mt < 2; mt++) {
#pragma unroll
        for (int hh = 0; hh < 2; hh++) {
            int row = wm * 32 + mt * 16 + g + hh * 8;
            if (EXPERT && m0 + row >= cnt) continue;
            int m = m0 + row;
            if (OMODE == 4) {
                int token = stok[row]; float w = swt[row]; int slot = ssl[row];
                float* dst = g_moe + ((size_t)slot * Sq + token) * Dm + n0;
#pragma unroll
                for (int nt = 0; nt < 8; nt++) {
                    int c = wn * 64 + nt * 8 + tig * 2;
                    *(float2*)(dst + c) =
                        make_float2(w * acc[mt][nt][2 * hh], w * acc[mt][nt][2 * hh + 1]);
                }
            } else if (OMODE == 5) {
                float* dst;
                if (n0 < HD)
                    dst = (float*)O0 + (size_t)kz * Sq * HD + (size_t)m * HD + n0;
                else if (n0 < HD + KVD)
                    dst = (float*)O1 + (size_t)kz * Sq * KVD + (size_t)m * KVD + (n0 - HD);
                else
                    dst = (float*)O2 + (size_t)kz * Sq * KVD + (size_t)m * KVD + (n0 - HD - KVD);
#pragma unroll
                for (int nt = 0; nt < 8; nt++) {
                    int c = wn * 64 + nt * 8 + tig * 2;
                    *(float2*)(dst + c) =
                        make_float2(acc[mt][nt][2 * hh], acc[mt][nt][2 * hh + 1]);
                }
            } else if (OMODE == 6) {
                __half* base = (n0 < Id) ? (__half*)O0 : (__half*)O1;
                int nloc = (n0 < Id) ? n0 : n0 - Id;
                __half* dst = base + (size_t)e * Sq * Id + (size_t)m * Id + nloc;
#pragma unroll
                for (int nt = 0; nt < 8; nt++) {
                    int c = wn * 64 + nt * 8 + tig * 2;
                    *(half2*)(dst + c) =
                        __floats2half2_rn(acc[mt][nt][2 * hh], acc[mt][nt][2 * hh + 1]);
                }
            } else {
                float* dst = (float*)O0 + (size_t)m * N + n0;
                const float* rs = (OMODE == 1) ? (res + (size_t)m * N + n0) : nullptr;
#pragma unroll
                for (int nt = 0; nt < 8; nt++) {
                    int c = wn * 64 + nt * 8 + tig * 2;
                    float2 v = make_float2(acc[mt][nt][2 * hh], acc[mt][nt][2 * hh + 1]);
                    if (OMODE == 1) { v.x += rs[c]; v.y += rs[c + 1]; }
                    *(float2*)(dst + c) = v;
                }
            }
        }
    }
}

// ================= flash attention (64-row q blocks, K/V double-buffered) =====
#define ATT_SMEM 195072
#define LDP 72

__global__ __launch_bounds__(256) void attn_mma() {
    extern __shared__ char smem[];
    const uint32_t sb = smem_u32(smem);
    const int qb = gridDim.x - 1 - blockIdx.x;
    const int h = blockIdx.y, kvh = h >> 2;
    const int tid = threadIdx.x, lane = tid & 31, wid = tid >> 5;
    const int wm = wid & 1, wn = wid >> 1;
    float* maxb = (float*)(smem + 192512);
    float* sumb = (float*)(smem + 193536);
    float* Mrow = (float*)(smem + 194560);
    float* Lrow = (float*)(smem + 194816);

#pragma unroll
    for (int j = 0; j < 8; j++) {
        int idx = tid + j * 256;
        int arr = idx >> 10, r = (idx >> 4) & 63, c = idx & 15;
        const __half* src = (arr ? g_ql : g_qh) + (size_t)(qb * 64 + r) * HD + h * DHd + c * 8;
        CP16(sb + arr * 17408 + r * 272 + c * 16, src);
    }
#pragma unroll
    for (int j = 0; j < 16; j++) {
        int idx = tid + j * 256;
        int arr = idx >> 10, r = (idx >> 4) & 63, c = idx & 15;
        const __half* s = arr == 0 ? g_kh2 : arr == 1 ? g_kl2 : arr == 2 ? g_vh : g_vl;
        CP16(sb + 34816 + arr * 17408 + r * 272 + c * 16,
             s + (size_t)r * KVD + kvh * DHd + c * 8);
    }
    CP_COMMIT();
    if (tid < 64) { Mrow[tid] = -INFINITY; Lrow[tid] = 0.f; }

    float oacc[2][4][4] = {};
    const int g = lane >> 2, tig = lane & 3;
    const int arow = wm * 32 + (lane & 7) + ((lane >> 3) & 1) * 8;
    const int brow16 = wn * 16 + (lane & 7) + 8 * (lane >> 4);

    for (int t = 0; t <= qb; t++) {
        const uint32_t B = sb + 34816 + (uint32_t)(t & 1) * 69632;
        if (t < qb) {
            uint32_t B1 = sb + 34816 + (uint32_t)((t + 1) & 1) * 69632;
#pragma unroll
            for (int j = 0; j < 16; j++) {
                int idx = tid + j * 256;
                int arr = idx >> 10, r = (idx >> 4) & 63, c = idx & 15;
                const __half* s = arr == 0 ? g_kh2 : arr == 1 ? g_kl2 : arr == 2 ? g_vh : g_vl;
                CP16(B1 + arr * 17408 + r * 272 + c * 16,
                     s + (size_t)((t + 1) * 64 + r) * KVD + kvh * DHd + c * 8);
            }
            CP_COMMIT();
            CP_WAIT(1);
        } else {
            CP_WAIT(0);
        }
        __syncthreads();

        float sacc[2][2][4] = {};
#pragma unroll
        for (int ks = 0; ks < 8; ks++) {
            uint32_t ah[2][4], al[2][4], bh[2][2], bl[2][2];
            int ak = ks * 16 + (lane >> 4) * 8;
            uint32_t ab = sb + (arow * 136 + ak) * 2;
            ldsm4(ah[0], ab);
            ldsm4(ah[1], ab + 16 * 272);
            ldsm4(al[0], ab + 17408);
            ldsm4(al[1], ab + 17408 + 16 * 272);
            int bk = ks * 16 + ((lane >> 3) & 1) * 8;
            uint32_t bb = B + (brow16 * 136 + bk) * 2;
            {
                uint32_t rr[4];
                ldsm4(rr, bb);
                bh[0][0] = rr[0]; bh[0][1] = rr[1];
                bh[1][0] = rr[2]; bh[1][1] = rr[3];
                ldsm4(rr, bb + 17408);
                bl[0][0] = rr[0]; bl[0][1] = rr[1];
                bl[1][0] = rr[2]; bl[1][1] = rr[3];
            }
            // 3 passes: hh, hl, lh (independent MMA chains within each pass)
#pragma unroll
            for (int mt = 0; mt < 2; mt++)
#pragma unroll
                for (int nf = 0; nf < 2; nf++)
                    mma16816(sacc[mt][nf], ah[mt], bh[nf]);
#pragma unroll
            for (int mt = 0; mt < 2; mt++)
#pragma unroll
                for (int nf = 0; nf < 2; nf++)
                    mma16816(sacc[mt][nf], ah[mt], bl[nf]);
#pragma unroll
            for (int mt = 0; mt < 2; mt++)
#pragma unroll
                for (int nf = 0; nf < 2; nf++)
                    mma16816(sacc[mt][nf], al[mt], bh[nf]);
        }

        if (t == qb) {
#pragma unroll
            for (int mt = 0; mt < 2; mt++)
#pragma unroll
                for (int nf = 0; nf < 2; nf++)
#pragma unroll
                    for (int i = 0; i < 4; i++) {
                        int row = wm * 32 + mt * 16 + g + (i >= 2 ? 8 : 0);
                        int col = wn * 16 + nf * 8 + tig * 2 + (i & 1);
                        if (col > row) sacc[mt][nf][i] = -INFINITY;
                    }
        }

        float rmax[2][2];
#pragma unroll
        for (int mt = 0; mt < 2; mt++)
#pragma unroll
            for (int hh = 0; hh < 2; hh++) {
                float m = fmaxf(fmaxf(sacc[mt][0][2 * hh], sacc[mt][0][2 * hh + 1]),
                                fmaxf(sacc[mt][1][2 * hh], sacc[mt][1][2 * hh + 1]));
                m = fmaxf(m, __shfl_xor_sync(0xffffffffu, m, 1));
                m = fmaxf(m, __shfl_xor_sync(0xffffffffu, m, 2));
                rmax[mt][hh] = m;
            }
        if (tig == 0) {
#pragma unroll
            for (int mt = 0; mt < 2; mt++) {
                int r = wm * 32 + mt * 16 + g;
                maxb[wn * 64 + r] = rmax[mt][0];
                maxb[wn * 64 + r + 8] = rmax[mt][1];
            }
        }
        __syncthreads();

        float alpha[2][2], mnew[2][2], rsum[2][2];
#pragma unroll
        for (int mt = 0; mt < 2; mt++)
#pragma unroll
            for (int hh = 0; hh < 2; hh++) {
                int r = wm * 32 + mt * 16 + g + hh * 8;
                float mo = Mrow[r];
                float mn = fmaxf(fmaxf(mo, maxb[r]),
                                 fmaxf(fmaxf(maxb[64 + r], maxb[128 + r]), maxb[192 + r]));
                mnew[mt][hh] = mn;
                alpha[mt][hh] = expf(mo - mn);
                rsum[mt][hh] = 0.f;
            }
#pragma unroll
        for (int mt = 0; mt < 2; mt++)
#pragma unroll
            for (int nf = 0; nf < 2; nf++)
#pragma unroll
                for (int hh = 0; hh < 2; hh++) {
                    float p0 = expf(sacc[mt][nf][2 * hh]     - mnew[mt][hh]);
                    float p1 = expf(sacc[mt][nf][2 * hh + 1] - mnew[mt][hh]);
                    rsum[mt][hh] += p0 + p1;
                    half2 hi, lo;
                    split2(p0, p1, hi, lo);
                    int r = wm * 32 + mt * 16 + g + hh * 8;
                    int c = wn * 16 + nf * 8 + tig * 2;
                    *(half2*)(smem + 174080 + (r * LDP + c) * 2) = hi;
                    *(half2*)(smem + 183296 + (r * LDP + c) * 2) = lo;
                }
#pragma unroll
        for (int mt = 0; mt < 2; mt++)
#pragma unroll
            for (int hh = 0; hh < 2; hh++) {
                float s = rsum[mt][hh];
                s += __shfl_xor_sync(0xffffffffu, s, 1);
                s += __shfl_xor_sync(0xffffffffu, s, 2);
                rsum[mt][hh] = s;
            }
        if (tig == 0) {
#pragma unroll
            for (int mt = 0; mt < 2; mt++) {
                int r = wm * 32 + mt * 16 + g;
                sumb[wn * 64 + r] = rsum[mt][0];
                sumb[wn * 64 + r + 8] = rsum[mt][1];
            }
        }
#pragma unroll
        for (int mt = 0; mt < 2; mt++)
#pragma unroll
            for (int vf = 0; vf < 4; vf++) {
                oacc[mt][vf][0] *= alpha[mt][0]; oacc[mt][vf][1] *= alpha[mt][0];
                oacc[mt][vf][2] *= alpha[mt][1]; oacc[mt][vf][3] *= alpha[mt][1];
            }
        __syncthreads();

        if (wn == 0 && tig == 0) {
#pragma unroll
            for (int mt = 0; mt < 2; mt++)
#pragma unroll
                for (int hh = 0; hh < 2; hh++) {
                    int r = wm * 32 + mt * 16 + g + hh * 8;
                    Lrow[r] = Lrow[r] * alpha[mt][hh]
                              + sumb[r] + sumb[64 + r] + sumb[128 + r] + sumb[192 + r];
                    Mrow[r] = mnew[mt][hh];
                }
        }

#pragma unroll
        for (int ks = 0; ks < 4; ks++) {
            uint32_t ph[2][4], pl[2][4], vh[4][2], vl[4][2];
            int ak = ks * 16 + (lane >> 4) * 8;
            uint32_t ab = sb + 174080 + (arow * LDP + ak) * 2;
            ldsm4(ph[0], ab);
            ldsm4(ph[1], ab + 16 * 144);
            ldsm4(pl[0], ab + 9216);
            ldsm4(pl[1], ab + 9216 + 16 * 144);
            int vk = ks * 16 + (lane & 7) + ((lane >> 3) & 1) * 8;
            int vn = wn * 32 + (lane >> 4) * 8;
            uint32_t vb = B + 34816 + (vk * 136 + vn) * 2;
#pragma unroll
            for (int ntp = 0; ntp < 2; ntp++) {
                uint32_t rr[4];
                ldsm4t(rr, vb + ntp * 32);
                vh[2 * ntp][0] = rr[0]; vh[2 * ntp][1] = rr[1];
                vh[2 * ntp + 1][0] = rr[2]; vh[2 * ntp + 1][1] = rr[3];
                ldsm4t(rr, vb + 17408 + ntp * 32);
                vl[2 * ntp][0] = rr[0]; vl[2 * ntp][1] = rr[1];
                vl[2 * ntp + 1][0] = rr[2]; vl[2 * ntp + 1][1] = rr[3];
            }
            // 3 passes: hh, hl, lh
#pragma unroll
            for (int mt = 0; mt < 2; mt++)
#pragma unroll
                for (int vf = 0; vf < 4; vf++)
                    mma16816(oacc[mt][vf], ph[mt], vh[vf]);
#pragma unroll
            for (int mt = 0; mt < 2; mt++)
#pragma unroll
                for (int vf = 0; vf < 4; vf++)
                    mma16816(oacc[mt][vf], ph[mt], vl[vf]);
#pragma unroll
            for (int mt = 0; mt < 2; mt++)
#pragma unroll
                for (int vf = 0; vf < 4; vf++)
                    mma16816(oacc[mt][vf], pl[mt], vh[vf]);
        }
        __syncthreads();
    }

#pragma unroll
    for (int mt = 0; mt < 2; mt++)
#pragma unroll
        for (int hh = 0; hh < 2; hh++) {
            int r = wm * 32 + mt * 16 + g + hh * 8;
            float inv = 1.f / Lrow[r];
#pragma unroll
            for (int vf = 0; vf < 4; vf++) {
                int c = wn * 32 + vf * 8 + tig * 2;
                float vx = oacc[mt][vf][2 * hh] * inv;
                float vy = oacc[mt][vf][2 * hh + 1] * inv;
                half2 hi, lo;
                split2(vx, vy, hi, lo);
                size_t dst = (size_t)(qb * 64 + r) * HD + h * DHd + c;
                *(half2*)&g_oh[dst] = hi;
                *(half2*)&g_ol[dst] = lo;
            }
        }
}

// ---------------- rmsnorm variants ----------------
__global__ __launch_bounds__(256) void rmsnorm_hl_k(const float* __restrict__ in,
                                                    const float* __restrict__ w,
                                                    __half* __restrict__ ohi,
                                                    __half* __restrict__ olo, int cols) {
    int row = blockIdx.x;
    const float* r = in + (size_t)row * cols;
    float ss = 0.f;
    for (int i = threadIdx.x; i < cols; i += 256) { float v = r[i]; ss += v * v; }
    __shared__ float red[256];
    red[threadIdx.x] = ss; __syncthreads();
    for (int st = 128; st > 0; st >>= 1) {
        if (threadIdx.x < st) red[threadIdx.x] += red[threadIdx.x + st];
        __syncthreads();
    }
    float scale = rsqrtf(red[0] / (float)cols + EPSf);
    for (int i = threadIdx.x; i < cols; i += 256) {
        float val = r[i] * scale * w[i];
        __half hv = __float2half_rn(val);
        ohi[(size_t)row * cols + i] = hv;
        olo[(size_t)row * cols + i] = __float2half_rn(val - __half2float(hv));
    }
}

__global__ __launch_bounds__(256) void rmsnorm_th_k(const float* __restrict__ in,
                                                    const float* __restrict__ w,
                                                    float* __restrict__ out,
                                                    __half* __restrict__ ohi, int cols) {
    int row = blockIdx.x;
    const float* r = in + (size_t)row * cols;
    float ss = 0.f;
    for (int i = threadIdx.x; i < cols; i += 256) { float v = r[i]; ss += v * v; }
    __shared__ float red[256];
    red[threadIdx.x] = ss; __syncthreads();
    for (int st = 128; st > 0; st >>= 1) {
        if (threadIdx.x < st) red[threadIdx.x] += red[threadIdx.x + st];
        __syncthreads();
    }
    float scale = rsqrtf(red[0] / (float)cols + EPSf);
    for (int i = threadIdx.x; i < cols; i += 256) {
        float val = r[i] * scale * w[i];
        out[(size_t)row * cols + i] = val;
        ohi[(size_t)row * cols + i] = __float2half_rn(val);
    }
}

// ---------------- fused: sum K-split partials + rmsnorm + RoPE + hi/lo (y=0 q, y=1 k),
//                  y=2: v combine + hi/lo split ----------------
__global__ __launch_bounds__(256) void rms_rope_k(
    const float* __restrict__ qsrc, const float* __restrict__ qw,
    __half* __restrict__ qhi, __half* __restrict__ qlo,
    const float* __restrict__ ksrc, const float* __restrict__ kw,
    __half* __restrict__ khi, __half* __restrict__ klo,
    const float* __restrict__ vsrc,
    __half* __restrict__ vhi, __half* __restrict__ vlo)
{
    __shared__ float rowbuf[2048];
    __shared__ float red[256];
    int row = blockIdx.x;
    int sel = blockIdx.y;
    if (sel == 2) {
        const float* v0 = vsrc + (size_t)row * KVD;
        const float* v1 = vsrc + (size_t)Sq * KVD + (size_t)row * KVD;
        for (int i = threadIdx.x; i < KVD; i += 256) {
            float val = v0[i] + v1[i];
            __half hv = __float2half_rn(val);
            vhi[(size_t)row * KVD + i] = hv;
            vlo[(size_t)row * KVD + i] = __float2half_rn(val - __half2float(hv));
        }
        return;
    }
    int isk = sel;
    int cols = isk ? KVD : HD;
    float scale = isk ? 1.0f : 0.08838834764831845f;
    const float* src = isk ? ksrc : qsrc;
    const float* src2 = src + (size_t)Sq * cols;
    const float* w = isk ? kw : qw;
    __half* hi = isk ? khi : qhi;
    __half* lo = isk ? klo : qlo;
    const float* r = src + (size_t)row * cols;
    const float* r2 = src2 + (size_t)row * cols;
    float ss = 0.f;
    for (int i = threadIdx.x; i < cols; i += 256) {
        float v = r[i] + r2[i];
        rowbuf[i] = v;
        ss += v * v;
    }
    red[threadIdx.x] = ss; __syncthreads();
    for (int st = 128; st > 0; st >>= 1) {
        if (threadIdx.x < st) red[threadIdx.x] += red[threadIdx.x + st];
        __syncthreads();
    }
    float sc = rsqrtf(red[0] / (float)cols + EPSf);
    for (int i = threadIdx.x; i < cols; i += 256) {
        int d = i & 127;
        float val = rowbuf[i] * sc * w[i];
        float outv;
        if (d < 32) {
            float inv = powf(1.0e6f, -(float)d / 32.f);
            float a = (float)row * inv;
            float v2 = rowbuf[i + 32] * sc * w[i + 32];
            outv = val * cosf(a) - v2 * sinf(a);
        } else if (d < 64) {
            int p = d - 32;
            float inv = powf(1.0e6f, -(float)p / 32.f);
            float a = (float)row * inv;
            float v2 = rowbuf[i - 32] * sc * w[i - 32];
            outv = val * cosf(a) + v2 * sinf(a);
        } else {
            outv = val;
        }
        outv *= scale;
        __half hv = __float2half_rn(outv);
        hi[(size_t)row * cols + i] = hv;
        lo[(size_t)row * cols + i] = __float2half_rn(outv - __half2float(hv));
    }
}

// ---------------- router ----------------
__global__ __launch_bounds__(256) void reset_k() {
    if (threadIdx.x < En) g_cnt[threadIdx.x] = 0;
}

__global__ __launch_bounds__(256) void router_k(const float* __restrict__ Tm,
                                                const float* __restrict__ rw,
                                                const float* __restrict__ rb) {
    int row = blockIdx.x, tid = threadIdx.x;
    const float* r = Tm + (size_t)row * Dm;
    float loc[En] = {};
    for (int d = tid; d < Dm; d += 256) {
        float x = r[d];
#pragma unroll
        for (int e = 0; e < En; e++) loc[e] += x * rw[d * En + e];
    }
    __shared__ float sred[256 * En];
#pragma unroll
    for (int e = 0; e < En; e++) sred[tid * En + e] = loc[e];
    __syncthreads();
    for (int st = 128; st > 0; st >>= 1) {
        if (tid < st)
#pragma unroll
            for (int e = 0; e < En; e++) sred[tid * En + e] += sred[(tid + st) * En + e];
        __syncthreads();
    }
    if (tid == 0) {
        float sig[En], scv[En];
#pragma unroll
        for (int e = 0; e < En; e++) {
            float l = sred[e];
            sig[e] = 1.f / (1.f + expf(-l));
            scv[e] = sig[e] + rb[e];
        }
        int i0 = 0;
#pragma unroll
        for (int e = 1; e < En; e++) if (scv[e] > scv[i0]) i0 = e;
        int i1 = -1;
#pragma unroll
        for (int e = 0; e < En; e++)
            if (e != i0 && (i1 < 0 || scv[e] > scv[i1])) i1 = e;
        float a0 = sig[i0], a1 = sig[i1], s = a0 + a1;
        float w0 = a0 / s, w1 = a1 / s;
        int p = atomicAdd(&g_cnt[i0], 1);
        g_ptok[i0 * Sq + p] = row; g_pw[i0 * Sq + p] = w0; g_pslot[i0 * Sq + p] = 0;
        p = atomicAdd(&g_cnt[i1], 1);
        g_ptok[i1 * Sq + p] = row; g_pw[i1 * Sq + p] = w1; g_pslot[i1 * Sq + p] = 1;
    }
}

// ---------------- act = silu(gate)*up (half in/out) ----------------
__global__ __launch_bounds__(256) void act_k() {
    int e = blockIdx.z;
    int cnt = g_cnt[e];
    int i = (blockIdx.x * 256 + threadIdx.x) * 8;
    int row = i >> 10;
    if (row >= cnt) return;
    size_t idx = (size_t)e * Sq * Id + i;
#pragma unroll
    for (int j = 0; j < 4; j++) {
        half2 gh = *(half2*)(g_gateh + idx + 2 * j);
        half2 uh = *(half2*)(g_uph + idx + 2 * j);
        float g0 = __low2float(gh), g1 = __high2float(gh);
        float u0 = __low2float(uh), u1 = __high2float(uh);
        float a0 = (g0 / (1.f + expf(-g0))) * u0;
        float a1 = (g1 / (1.f + expf(-g1))) * u1;
        *(half2*)(g_acth + idx + 2 * j) = __floats2half2_rn(a0, a1);
    }
}

// ---------------- final: out = x1 + moe0 + moe1 (float4) ----------------
__global__ __launch_bounds__(256) void final_add_k(float* __restrict__ out) {
    int i = (blockIdx.x * 256 + threadIdx.x) * 4;
    float4 a = *(float4*)(out + i);
    float4 b = *(float4*)(g_moe + i);
    float4 c = *(float4*)(g_moe + (size_t)Sq * Dm + i);
    a.x += b.x + c.x; a.y += b.y + c.y; a.z += b.z + c.z; a.w += b.w + c.w;
    *(float4*)(out + i) = a;
}

// ---------------- host orchestration ----------------
extern "C" void kernel_launch(void* const* d_in, const int* in_sizes, int n_in,
                              void* d_out, int out_size) {
    const float* x    = (const float*)d_in[0];
    const float* ln1  = (const float*)d_in[1];
    const float* ln2  = (const float*)d_in[2];
    const float* wq   = (const float*)d_in[3];
    const float* wk   = (const float*)d_in[4];
    const float* wv   = (const float*)d_in[5];
    const float* wo   = (const float*)d_in[6];
    const float* qn   = (const float*)d_in[7];
    const float* kn   = (const float*)d_in[8];
    const float* rw   = (const float*)d_in[9];
    const float* rb   = (const float*)d_in[10];
    const float* wg   = (const float*)d_in[11];
    const float* wu   = (const float*)d_in[12];
    const float* wd   = (const float*)d_in[13];
    float* out = (float*)d_out;

    float *pq, *pk, *pv, *pt;
    cudaGetSymbolAddress((void**)&pq, g_q);
    cudaGetSymbolAddress((void**)&pk, g_k);
    cudaGetSymbolAddress((void**)&pv, g_v);
    cudaGetSymbolAddress((void**)&pt, g_t);
    __half *hh, *hl, *qh, *ql, *kh, *kl, *vh, *vl, *oh, *ol, *th, *gateh, *uph, *acth;
    cudaGetSymbolAddress((void**)&hh, g_hh);   cudaGetSymbolAddress((void**)&hl, g_hl);
    cudaGetSymbolAddress((void**)&qh, g_qh);   cudaGetSymbolAddress((void**)&ql, g_ql);
    cudaGetSymbolAddress((void**)&kh, g_kh2);  cudaGetSymbolAddress((void**)&kl, g_kl2);
    cudaGetSymbolAddress((void**)&vh, g_vh);   cudaGetSymbolAddress((void**)&vl, g_vl);
    cudaGetSymbolAddress((void**)&oh, g_oh);   cudaGetSymbolAddress((void**)&ol, g_ol);
    cudaGetSymbolAddress((void**)&th, g_th);
    cudaGetSymbolAddress((void**)&gateh, g_gateh);
    cudaGetSymbolAddress((void**)&uph, g_uph);
    cudaGetSymbolAddress((void**)&acth, g_acth);
    __half *qkvh, *qkvl, *woh, *wol, *guh, *wdh;
    cudaGetSymbolAddress((void**)&qkvh, w_qkvh); cudaGetSymbolAddress((void**)&qkvl, w_qkvl);
    cudaGetSymbolAddress((void**)&woh, w_oh);    cudaGetSymbolAddress((void**)&wol, w_ol);
    cudaGetSymbolAddress((void**)&guh, w_guh);   cudaGetSymbolAddress((void**)&wdh, w_dh);

    cudaFuncSetAttribute(attn_mma, cudaFuncAttributeMaxDynamicSharedMemorySize, ATT_SMEM);
    cudaFuncSetAttribute(gemm_mma2<false,false,true,5,2>, cudaFuncAttributeMaxDynamicSharedMemorySize, SM_SPLIT);
    cudaFuncSetAttribute(gemm_mma2<false,false,true,1,1>, cudaFuncAttributeMaxDynamicSharedMemorySize, SM_SPLIT);
    cudaFuncSetAttribute(gemm_mma2<true ,true ,false,6,1>, cudaFuncAttributeMaxDynamicSharedMemorySize, SM_SINGLE);
    cudaFuncSetAttribute(gemm_mma2<false,true ,false,4,1>, cudaFuncAttributeMaxDynamicSharedMemorySize, SM_SINGLE);

    // 0. weight conversions
    conv_split_all<<<dim3(2048, 4), 256>>>(wq, wk, wv, wo, qkvh, qkvl, woh, wol);
    conv_single_all<<<dim3(4096, 3), 256>>>(wg, wu, wd, guh, wdh);

    // 1. h = rmsnorm(x, ln1) -> hi/lo halves
    rmsnorm_hl_k<<<Sq, 256>>>(x, ln1, hh, hl, Dm);
    // 2. fused QKV projection, K-split x2 (partial fp32 outputs)
    gemm_mma2<false,false,true,5,2><<<dim3(3072/128, Sq/128, 2), 256, SM_SPLIT>>>(
        hh, hl, qkvh, qkvl, pq, pk, pv, nullptr, nullptr, Sq, 3072, Dm);
    // 3+4. sum partials + rmsnorm + RoPE + split (y=0 q, y=1 k); y=2 v combine+split
    rms_rope_k<<<dim3(Sq, 3), 256>>>(pq, qn, qh, ql, pk, kn, kh, kl, pv, vh, vl);
    // 5. attention (64-row q blocks, pipelined KV)
    attn_mma<<<dim3(Sq/64, Hn), 256, ATT_SMEM>>>();
    // 6. x1 = x + o @ wo
    gemm_mma2<false,false,true,1,1><<<dim3(Dm/128, Sq/128), 256, SM_SPLIT>>>(
        oh, ol, woh, wol, out, nullptr, nullptr, nullptr, x, Sq, Dm, HD);
    // 7. t = rmsnorm(x1, ln2) -> fp32 + hi
    rmsnorm_th_k<<<Sq, 256>>>(out, ln2, pt, th, Dm);
    // 8. routing
    reset_k<<<1, 256>>>();
    router_k<<<Sq, 256>>>(pt, rw, rb);
    // 9. fused expert gate+up (gathered, half output)
    gemm_mma2<true,true,false,6,1><<<dim3(2048/128, Sq/128, En), 256, SM_SINGLE>>>(
        th, nullptr, guh, nullptr, gateh, uph, nullptr, nullptr, nullptr, Sq, 2048, Dm);
    // 10. act (half in/out)
    act_k<<<dim3((Sq*Id)/2048, 1, En), 256>>>();
    // 11. down GEMM + weighted scatter
    gemm_mma2<false,true,false,4,1><<<dim3(Dm/128, Sq/128, En), 256, SM_SINGLE>>>(
        acth, nullptr, wdh, nullptr, nullptr, nullptr, nullptr, nullptr, nullptr, Sq, Dm, Id);
    // 12. out = x1 + moe
    final_add_k<<<(Sq*Dm)/1024, 256>>>(out);
}

// round 14
// speedup vs baseline: 1.5999x; 1.5999x over previous
#include <cuda_runtime.h>
#include <cuda_fp16.h>
#include <math.h>
#include <stdint.h>

// ---------------- problem constants ----------------
#define Sq   2048
#define Dm   2048
#define Hn   16
#define KVn  4
#define DHd  128
#define En   8
#define Id   1024
#define HD   2048
#define KVD  512
#define EPSf 1e-6f

// ---------------- static device scratch ----------------
__device__ float g_q   [2*Sq*HD];    // two K-split partials
__device__ float g_k   [2*Sq*KVD];
__device__ float g_v   [2*Sq*KVD];
__device__ float g_t   [Sq*Dm];
__device__ float g_moe [2*Sq*Dm];
__device__ int   g_cnt [En];
__device__ int   g_ptok[En*Sq];
__device__ float g_pw  [En*Sq];
__device__ int   g_pslot[En*Sq];
// fp16 activations
__device__ __half g_hh [Sq*Dm];
__device__ __half g_hl [Sq*Dm];
__device__ __half g_qh [Sq*HD];
__device__ __half g_ql [Sq*HD];
__device__ __half g_kh2[Sq*KVD];
__device__ __half g_kl2[Sq*KVD];
__device__ __half g_vh [Sq*KVD];
__device__ __half g_vl [Sq*KVD];
__device__ __half g_oh [Sq*HD];
__device__ __half g_ol [Sq*HD];
__device__ __half g_th [Sq*Dm];
__device__ __half g_gateh[En*Sq*Id];
__device__ __half g_uph  [En*Sq*Id];
__device__ __half g_acth [En*Sq*Id];
// fp16 weights (qkv concatenated: cols 0-2047 q, 2048-2559 k, 2560-3071 v)
__device__ __half w_qkvh[Dm*3072];
__device__ __half w_qkvl[Dm*3072];
__device__ __half w_oh[HD*Dm];
__device__ __half w_ol[HD*Dm];
__device__ __half w_guh[En*Dm*2048];   // cols 0-1023 gate, 1024-2047 up
__device__ __half w_dh [En*Id*Dm];

// ---------------- side stream for convert overlap (host objects only) ----------------
static cudaStream_t g_s2;
static cudaEvent_t g_evFork, g_evJoin;
static struct StreamInit {
    StreamInit() {
        cudaStreamCreateWithFlags(&g_s2, cudaStreamNonBlocking);
        cudaEventCreateWithFlags(&g_evFork, cudaEventDisableTiming);
        cudaEventCreateWithFlags(&g_evJoin, cudaEventDisableTiming);
    }
} g_streamInit;

// ---------------- helpers ----------------
__device__ __forceinline__ uint32_t smem_u32(const void* p) {
    uint32_t a;
    asm("{ .reg .u64 t; cvta.to.shared.u64 t, %1; cvt.u32.u64 %0, t; }" : "=r"(a) : "l"(p));
    return a;
}
__device__ __forceinline__ void ldsm4(uint32_t* r, uint32_t a) {
    asm volatile("ldmatrix.sync.aligned.m8n8.x4.shared.b16 {%0,%1,%2,%3}, [%4];"
                 : "=r"(r[0]), "=r"(r[1]), "=r"(r[2]), "=r"(r[3]) : "r"(a));
}
__device__ __forceinline__ void ldsm4t(uint32_t* r, uint32_t a) {
    asm volatile("ldmatrix.sync.aligned.m8n8.x4.trans.shared.b16 {%0,%1,%2,%3}, [%4];"
                 : "=r"(r[0]), "=r"(r[1]), "=r"(r[2]), "=r"(r[3]) : "r"(a));
}
__device__ __forceinline__ void mma16816(float* d, const uint32_t* a, const uint32_t* b) {
    asm volatile("mma.sync.aligned.m16n8k16.row.col.f32.f16.f16.f32 "
                 "{%0,%1,%2,%3}, {%4,%5,%6,%7}, {%8,%9}, {%0,%1,%2,%3};"
                 : "+f"(d[0]), "+f"(d[1]), "+f"(d[2]), "+f"(d[3])
                 : "r"(a[0]), "r"(a[1]), "r"(a[2]), "r"(a[3]), "r"(b[0]), "r"(b[1]));
}
__device__ __forceinline__ void split2(float x, float y, half2& hi, half2& lo) {
    hi = __floats2half2_rn(x, y);
    lo = __floats2half2_rn(x - __low2float(hi), y - __high2float(hi));
}
#define CP16(dst, src) \
    asm volatile("cp.async.cg.shared.global [%0], [%1], 16;" :: "r"((uint32_t)(dst)), "l"(src))
#define CP_COMMIT() asm volatile("cp.async.commit_group;" ::: "memory")
#define CP_WAIT(n)  asm volatile("cp.async.wait_group %0;" :: "n"(n) : "memory")

// ---------------- fused weight converts ----------------
__global__ __launch_bounds__(256) void conv_split_all(
    const float* wq, const float* wk, const float* wv, const float* wo,
    __half* qkvh, __half* qkvl, __half* woh, __half* wol)
{
    int y = blockIdx.y;
    int nblk = (y == 0 || y == 3) ? 2048 : 512;
    if (blockIdx.x >= nblk) return;
    const float* s = y == 0 ? wq : y == 1 ? wk : y == 2 ? wv : wo;
    size_t base = ((size_t)blockIdx.x * 256 + threadIdx.x) * 8;
#pragma unroll
    for (int j = 0; j < 2; j++) {
        size_t i = base + 4 * j;
        float4 v = *(const float4*)(s + i);
        half2 a0, b0, a1, b1;
        split2(v.x, v.y, a0, b0); split2(v.z, v.w, a1, b1);
        size_t d;
        __half *hi, *lo;
        if (y == 3) { d = i; hi = woh; lo = wol; }
        else if (y == 0) { size_t r = i >> 11, c = i & 2047; d = r * 3072 + c; hi = qkvh; lo = qkvl; }
        else { size_t r = i / 512, c = i % 512; d = r * 3072 + (y == 1 ? 2048 : 2560) + c; hi = qkvh; lo = qkvl; }
        *(half2*)(hi + d) = a0; *(half2*)(hi + d + 2) = a1;
        *(half2*)(lo + d) = b0; *(half2*)(lo + d + 2) = b1;
    }
}
__global__ __launch_bounds__(256) void conv_single_all(
    const float* wg, const float* wu, const float* wd,
    __half* guh, __half* wdh)
{
    int y = blockIdx.y;
    const float* s = y == 0 ? wg : y == 1 ? wu : wd;
    size_t base = ((size_t)blockIdx.x * 256 + threadIdx.x) * 8;
#pragma unroll
    for (int j = 0; j < 2; j++) {
        size_t i = base + 4 * j;
        float4 v = *(const float4*)(s + i);
        half2 h0 = __floats2half2_rn(v.x, v.y);
        half2 h1 = __floats2half2_rn(v.z, v.w);
        size_t d;
        __half* dst;
        if (y == 2) { d = i; dst = wdh; }
        else {
            size_t e = i / ((size_t)Dm * Id);
            size_t rem = i % ((size_t)Dm * Id);
            size_t r = rem >> 10, c = rem & 1023;
            d = e * (size_t)Dm * 2048 + r * 2048 + (y ? 1024 : 0) + c;
            dst = guh;
        }
        *(half2*)(dst + d) = h0; *(half2*)(dst + d + 2) = h1;
    }
}

// ================= fp16 mma GEMM, multi-stage cp.async pipeline =================
#define AT_SZ 10240     // 128 rows x 80B
#define BT_SZ 8704      // 32 rows x 272B
#define SM_SPLIT  (3 * (2*AT_SZ + 2*BT_SZ))          // 113664, no header
#define SM_SINGLE (2048 + 4 * (AT_SZ + BT_SZ))       // 77824, with header

// OMODE: 0 f32, 1 f32+res, 4 moe-scatter, 5 qkv triple (K-split partials), 6 gate/up pair
template<bool GATHER, bool EXPERT, bool SPLIT, int OMODE, int KSPLIT>
__global__ __launch_bounds__(256, 2) void gemm_mma2(
    const __half* __restrict__ Ah, const __half* __restrict__ Al,
    const __half* __restrict__ Bh, const __half* __restrict__ Bl,
    void* __restrict__ O0, void* __restrict__ O1,
    void* __restrict__ O2, void* __restrict__ O3,
    const float* __restrict__ res,
    int M, int N, int K)
{
    extern __shared__ char smem[];
    constexpr int STAGES = SPLIT ? 3 : 4;
    constexpr bool HDR = (GATHER || OMODE == 4);
    const int tid = threadIdx.x, lane = tid & 31, wid = tid >> 5;
    const int wm = wid & 3, wn = wid >> 2;
    const int STG  = SPLIT ? (2 * AT_SZ + 2 * BT_SZ) : (AT_SZ + BT_SZ);
    const int BOFF = SPLIT ? 2 * AT_SZ : AT_SZ;

    int e = 0, cnt = M;
    const __half* Ahe = Ah;
    const __half* Bhe = Bh;
    const __half* Ble = Bl;
    const int kz = (KSPLIT == 2) ? blockIdx.z : 0;
    const int Keff = K / KSPLIT;
    const int kbase = kz * Keff;
    if (EXPERT) {
        e = blockIdx.z;
        cnt = g_cnt[e];
        Bhe = Bh + (size_t)e * K * N;
        if (SPLIT) Ble = Bl + (size_t)e * K * N;
        if (!GATHER) Ahe = Ah + (size_t)e * Sq * K;
    }
    const int m0 = blockIdx.y * 128;
    if (EXPERT && m0 >= cnt) return;
    const int n0 = blockIdx.x * 128;

    int*   stok = (int*)smem;
    float* swt  = (float*)(smem + 512);
    int*   ssl  = (int*)(smem + 1024);
    if (HDR) {
        if (tid < 128) {
            int r = m0 + tid;
            bool ok = r < cnt;
            stok[tid] = ok ? g_ptok[e * Sq + r] : 0;
            if (OMODE == 4) {
                swt[tid] = ok ? g_pw[e * Sq + r] : 0.f;
                ssl[tid] = ok ? g_pslot[e * Sq + r] : 0;
            }
        }
        __syncthreads();
    }
    const uint32_t sb = smem_u32(smem);
    const uint32_t tb = sb + (HDR ? 2048 : 0);
    const int T = Keff / 32;

#define ISSUE(it) do { \
        int _k0 = kbase + (it) * 32; \
        uint32_t _s0 = tb + (uint32_t)((it) % STAGES) * STG; \
        _Pragma("unroll") \
        for (int _j = 0; _j < 2; _j++) { \
            int _idx = tid + _j * 256; \
            int _row = _idx >> 2, _c = _idx & 3; \
            int _gr = GATHER ? stok[_row] : (m0 + _row); \
            CP16(_s0 + _row * 80 + _c * 16, Ahe + (size_t)_gr * K + _k0 + _c * 8); \
            if (SPLIT) CP16(_s0 + AT_SZ + _row * 80 + _c * 16, Al + (size_t)_gr * K + _k0 + _c * 8); \
        } \
        _Pragma("unroll") \
        for (int _j = 0; _j < 2; _j++) { \
            int _idx = tid + _j * 256; \
            int _row = _idx >> 4, _c = _idx & 15; \
            CP16(_s0 + BOFF + _row * 272 + _c * 16, Bhe + (size_t)(_k0 + _row) * N + n0 + _c * 8); \
            if (SPLIT) CP16(_s0 + BOFF + BT_SZ + _row * 272 + _c * 16, \
                            Ble + (size_t)(_k0 + _row) * N + n0 + _c * 8); \
        } \
        CP_COMMIT(); \
    } while (0)

#pragma unroll
    for (int p = 0; p < STAGES - 1; p++) {
        if (p < T) ISSUE(p); else CP_COMMIT();
    }

    float acc[2][8][4] = {};
    for (int it = 0; it < T; ++it) {
        CP_WAIT(STAGES - 2);
        __syncthreads();
        {
            int nx = it + STAGES - 1;
            if (nx < T) ISSUE(nx); else CP_COMMIT();
        }
        uint32_t s0 = tb + (uint32_t)(it % STAGES) * STG;
#pragma unroll
        for (int ks = 0; ks < 2; ks++) {
            uint32_t ah[2][4], al[2][4], bh[8][2], bl[8][2];
            int am = wm * 32 + (lane & 7) + ((lane >> 3) & 1) * 8;
            int ak = ks * 16 + (lane >> 4) * 8;
            uint32_t ab = s0 + am * 80 + ak * 2;
            ldsm4(ah[0], ab);
            ldsm4(ah[1], ab + 16 * 80);
            if (SPLIT) { ldsm4(al[0], ab + AT_SZ); ldsm4(al[1], ab + AT_SZ + 16 * 80); }
            int bk = ks * 16 + (lane & 7) + ((lane >> 3) & 1) * 8;
            int bn = wn * 64 + (lane >> 4) * 8;
            uint32_t bb = s0 + BOFF + bk * 272 + bn * 2;
#pragma unroll
            for (int t = 0; t < 4; t++) {
                uint32_t rr[4];
                ldsm4t(rr, bb + t * 32);
                bh[2 * t][0] = rr[0]; bh[2 * t][1] = rr[1];
                bh[2 * t + 1][0] = rr[2]; bh[2 * t + 1][1] = rr[3];
                if (SPLIT) {
                    ldsm4t(rr, bb + BT_SZ + t * 32);
                    bl[2 * t][0] = rr[0]; bl[2 * t][1] = rr[1];
                    bl[2 * t + 1][0] = rr[2]; bl[2 * t + 1][1] = rr[3];
                }
            }
#pragma unroll
            for (int mt = 0; mt < 2; mt++)
#pragma unroll
                for (int nt = 0; nt < 8; nt++) {
                    mma16816(acc[mt][nt], ah[mt], bh[nt]);
                    if (SPLIT) {
                        mma16816(acc[mt][nt], ah[mt], bl[nt]);
                        mma16816(acc[mt][nt], al[mt], bh[nt]);
                    }
                }
        }
    }
#undef ISSUE

    const int g = lane >> 2, tig = lane & 3;
#pragma unroll
    for (int mt = 0; mt < 2; mt++) {
#pragma unroll
        for (int hh = 0; hh < 2; hh++) {
            int row = wm * 32 + mt * 16 + g + hh * 8;
            if (EXPERT && m0 + row >= cnt) continue;
            int m = m0 + row;
            if (OMODE == 4) {
                int token = stok[row]; float w = swt[row]; int slot = ssl[row];
                float* dst = g_moe + ((size_t)slot * Sq + token) * Dm + n0;
#pragma unroll
                for (int nt = 0; nt < 8; nt++) {
                    int c = wn * 64 + nt * 8 + tig * 2;
                    *(float2*)(dst + c) =
                        make_float2(w * acc[mt][nt][2 * hh], w * acc[mt][nt][2 * hh + 1]);
                }
            } else if (OMODE == 5) {
                float* dst;
                if (n0 < HD)
                    dst = (float*)O0 + (size_t)kz * Sq * HD + (size_t)m * HD + n0;
                else if (n0 < HD + KVD)
                    dst = (float*)O1 + (size_t)kz * Sq * KVD + (size_t)m * KVD + (n0 - HD);
                else
                    dst = (float*)O2 + (size_t)kz * Sq * KVD + (size_t)m * KVD + (n0 - HD - KVD);
#pragma unroll
                for (int nt = 0; nt < 8; nt++) {
                    int c = wn * 64 + nt * 8 + tig * 2;
                    *(float2*)(dst + c) =
                        make_float2(acc[mt][nt][2 * hh], acc[mt][nt][2 * hh + 1]);
                }
            } else if (OMODE == 6) {
                __half* base = (n0 < Id) ? (__half*)O0 : (__half*)O1;
                int nloc = (n0 < Id) ? n0 : n0 - Id;
                __half* dst = base + (size_t)e * Sq * Id + (size_t)m * Id + nloc;
#pragma unroll
                for (int nt = 0; nt < 8; nt++) {
                    int c = wn * 64 + nt * 8 + tig * 2;
                    *(half2*)(dst + c) =
                        __floats2half2_rn(acc[mt][nt][2 * hh], acc[mt][nt][2 * hh + 1]);
                }
            } else {
                float* dst = (float*)O0 + (size_t)m * N + n0;
                const float* rs = (OMODE == 1) ? (res + (size_t)m * N + n0) : nullptr;
#pragma unroll
                for (int nt = 0; nt < 8; nt++) {
                    int c = wn * 64 + nt * 8 + tig * 2;
                    float2 v = make_float2(acc[mt][nt][2 * hh], acc[mt][nt][2 * hh + 1]);
                    if (OMODE == 1) { v.x += rs[c]; v.y += rs[c + 1]; }
                    *(float2*)(dst + c) = v;
                }
            }
        }
    }
}

// ================= flash attention (64-row q blocks, K/V double-buffered) =====
#define ATT_SMEM 195072
#define LDP 72

__global__ __launch_bounds__(256) void attn_mma() {
    extern __shared__ char smem[];
    const uint32_t sb = smem_u32(smem);
    const int qb = gridDim.x - 1 - blockIdx.x;
    const int h = blockIdx.y, kvh = h >> 2;
    const int tid = threadIdx.x, lane = tid & 31, wid = tid >> 5;
    const int wm = wid & 1, wn = wid >> 1;
    float* maxb = (float*)(smem + 192512);
    float* sumb = (float*)(smem + 193536);
    float* Mrow = (float*)(smem + 194560);
    float* Lrow = (float*)(smem + 194816);

#pragma unroll
    for (int j = 0; j < 8; j++) {
        int idx = tid + j * 256;
        int arr = idx >> 10, r = (idx >> 4) & 63, c = idx & 15;
        const __half* src = (arr ? g_ql : g_qh) + (size_t)(qb * 64 + r) * HD + h * DHd + c * 8;
        CP16(sb + arr * 17408 + r * 272 + c * 16, src);
    }
#pragma unroll
    for (int j = 0; j < 16; j++) {
        int idx = tid + j * 256;
        int arr = idx >> 10, r = (idx >> 4) & 63, c = idx & 15;
        const __half* s = arr == 0 ? g_kh2 : arr == 1 ? g_kl2 : arr == 2 ? g_vh : g_vl;
        CP16(sb + 34816 + arr * 17408 + r * 272 + c * 16,
             s + (size_t)r * KVD + kvh * DHd + c * 8);
    }
    CP_COMMIT();
    if (tid < 64) { Mrow[tid] = -INFINITY; Lrow[tid] = 0.f; }

    float oacc[2][4][4] = {};
    const int g = lane >> 2, tig = lane & 3;
    const int arow = wm * 32 + (lane & 7) + ((lane >> 3) & 1) * 8;
    const int brow16 = wn * 16 + (lane & 7) + 8 * (lane >> 4);

    for (int t = 0; t <= qb; t++) {
        const uint32_t B = sb + 34816 + (uint32_t)(t & 1) * 69632;
        if (t < qb) {
            uint32_t B1 = sb + 34816 + (uint32_t)((t + 1) & 1) * 69632;
#pragma unroll
            for (int j = 0; j < 16; j++) {
                int idx = tid + j * 256;
                int arr = idx >> 10, r = (idx >> 4) & 63, c = idx & 15;
                const __half* s = arr == 0 ? g_kh2 : arr == 1 ? g_kl2 : arr == 2 ? g_vh : g_vl;
                CP16(B1 + arr * 17408 + r * 272 + c * 16,
                     s + (size_t)((t + 1) * 64 + r) * KVD + kvh * DHd + c * 8);
            }
            CP_COMMIT();
            CP_WAIT(1);
        } else {
            CP_WAIT(0);
        }
        __syncthreads();

        float sacc[2][2][4] = {};
#pragma unroll
        for (int ks = 0; ks < 8; ks++) {
            uint32_t ah[2][4], al[2][4], bh[2][2], bl[2][2];
            int ak = ks * 16 + (lane >> 4) * 8;
            uint32_t ab = sb + (arow * 136 + ak) * 2;
            ldsm4(ah[0], ab);
            ldsm4(ah[1], ab + 16 * 272);
            ldsm4(al[0], ab + 17408);
            ldsm4(al[1], ab + 17408 + 16 * 272);
            int bk = ks * 16 + ((lane >> 3) & 1) * 8;
            uint32_t bb = B + (brow16 * 136 + bk) * 2;
            {
                uint32_t rr[4];
                ldsm4(rr, bb);
                bh[0][0] = rr[0]; bh[0][1] = rr[1];
                bh[1][0] = rr[2]; bh[1][1] = rr[3];
                ldsm4(rr, bb + 17408);
                bl[0][0] = rr[0]; bl[0][1] = rr[1];
                bl[1][0] = rr[2]; bl[1][1] = rr[3];
            }
#pragma unroll
            for (int mt = 0; mt < 2; mt++)
#pragma unroll
                for (int nf = 0; nf < 2; nf++) {
                    mma16816(sacc[mt][nf], ah[mt], bh[nf]);
                    mma16816(sacc[mt][nf], ah[mt], bl[nf]);
                    mma16816(sacc[mt][nf], al[mt], bh[nf]);
                }
        }

        if (t == qb) {
#pragma unroll
            for (int mt = 0; mt < 2; mt++)
#pragma unroll
                for (int nf = 0; nf < 2; nf++)
#pragma unroll
                    for (int i = 0; i < 4; i++) {
                        int row = wm * 32 + mt * 16 + g + (i >= 2 ? 8 : 0);
                        int col = wn * 16 + nf * 8 + tig * 2 + (i & 1);
                        if (col > row) sacc[mt][nf][i] = -INFINITY;
                    }
        }

        float rmax[2][2];
#pragma unroll
        for (int mt = 0; mt < 2; mt++)
#pragma unroll
            for (int hh = 0; hh < 2; hh++) {
                float m = fmaxf(fmaxf(sacc[mt][0][2 * hh], sacc[mt][0][2 * hh + 1]),
                                fmaxf(sacc[mt][1][2 * hh], sacc[mt][1][2 * hh + 1]));
                m = fmaxf(m, __shfl_xor_sync(0xffffffffu, m, 1));
                m = fmaxf(m, __shfl_xor_sync(0xffffffffu, m, 2));
                rmax[mt][hh] = m;
            }
        if (tig == 0) {
#pragma unroll
            for (int mt = 0; mt < 2; mt++) {
                int r = wm * 32 + mt * 16 + g;
                maxb[wn * 64 + r] = rmax[mt][0];
                maxb[wn * 64 + r + 8] = rmax[mt][1];
            }
        }
        __syncthreads();

        float alpha[2][2], mnew[2][2], rsum[2][2];
#pragma unroll
        for (int mt = 0; mt < 2; mt++)
#pragma unroll
            for (int hh = 0; hh < 2; hh++) {
                int r = wm * 32 + mt * 16 + g + hh * 8;
                float mo = Mrow[r];
                float mn = fmaxf(fmaxf(mo, maxb[r]),
                                 fmaxf(fmaxf(maxb[64 + r], maxb[128 + r]), maxb[192 + r]));
                mnew[mt][hh] = mn;
                alpha[mt][hh] = expf(mo - mn);
                rsum[mt][hh] = 0.f;
            }
#pragma unroll
        for (int mt = 0; mt < 2; mt++)
#pragma unroll
            for (int nf = 0; nf < 2; nf++)
#pragma unroll
                for (int hh = 0; hh < 2; hh++) {
                    float p0 = expf(sacc[mt][nf][2 * hh]     - mnew[mt][hh]);
                    float p1 = expf(sacc[mt][nf][2 * hh + 1] - mnew[mt][hh]);
                    rsum[mt][hh] += p0 + p1;
                    half2 hi, lo;
                    split2(p0, p1, hi, lo);
                    int r = wm * 32 + mt * 16 + g + hh * 8;
                    int c = wn * 16 + nf * 8 + tig * 2;
                    *(half2*)(smem + 174080 + (r * LDP + c) * 2) = hi;
                    *(half2*)(smem + 183296 + (r * LDP + c) * 2) = lo;
                }
#pragma unroll
        for (int mt = 0; mt < 2; mt++)
#pragma unroll
            for (int hh = 0; hh < 2; hh++) {
                float s = rsum[mt][hh];
                s += __shfl_xor_sync(0xffffffffu, s, 1);
                s += __shfl_xor_sync(0xffffffffu, s, 2);
                rsum[mt][hh] = s;
            }
        if (tig == 0) {
#pragma unroll
            for (int mt = 0; mt < 2; mt++) {
                int r = wm * 32 + mt * 16 + g;
                sumb[wn * 64 + r] = rsum[mt][0];
                sumb[wn * 64 + r + 8] = rsum[mt][1];
            }
        }
#pragma unroll
        for (int mt = 0; mt < 2; mt++)
#pragma unroll
            for (int vf = 0; vf < 4; vf++) {
                oacc[mt][vf][0] *= alpha[mt][0]; oacc[mt][vf][1] *= alpha[mt][0];
                oacc[mt][vf][2] *= alpha[mt][1]; oacc[mt][vf][3] *= alpha[mt][1];
            }
        __syncthreads();

        if (wn == 0 && tig == 0) {
#pragma unroll
            for (int mt = 0; mt < 2; mt++)
#pragma unroll
                for (int hh = 0; hh < 2; hh++) {
                    int r = wm * 32 + mt * 16 + g + hh * 8;
                    Lrow[r] = Lrow[r] * alpha[mt][hh]
                              + sumb[r] + sumb[64 + r] + sumb[128 + r] + sumb[192 + r];
                    Mrow[r] = mnew[mt][hh];
                }
        }

#pragma unroll
        for (int ks = 0; ks < 4; ks++) {
            uint32_t ph[2][4], pl[2][4], vh[4][2], vl[4][2];
            int ak = ks * 16 + (lane >> 4) * 8;
            uint32_t ab = sb + 174080 + (arow * LDP + ak) * 2;
            ldsm4(ph[0], ab);
            ldsm4(ph[1], ab + 16 * 144);
            ldsm4(pl[0], ab + 9216);
            ldsm4(pl[1], ab + 9216 + 16 * 144);
            int vk = ks * 16 + (lane & 7) + ((lane >> 3) & 1) * 8;
            int vn = wn * 32 + (lane >> 4) * 8;
            uint32_t vb = B + 34816 + (vk * 136 + vn) * 2;
#pragma unroll
            for (int ntp = 0; ntp < 2; ntp++) {
                uint32_t rr[4];
                ldsm4t(rr, vb + ntp * 32);
                vh[2 * ntp][0] = rr[0]; vh[2 * ntp][1] = rr[1];
                vh[2 * ntp + 1][0] = rr[2]; vh[2 * ntp + 1][1] = rr[3];
                ldsm4t(rr, vb + 17408 + ntp * 32);
                vl[2 * ntp][0] = rr[0]; vl[2 * ntp][1] = rr[1];
                vl[2 * ntp + 1][0] = rr[2]; vl[2 * ntp + 1][1] = rr[3];
            }
#pragma unroll
            for (int mt = 0; mt < 2; mt++)
#pragma unroll
                for (int vf = 0; vf < 4; vf++) {
                    mma16816(oacc[mt][vf], ph[mt], vh[vf]);
                    mma16816(oacc[mt][vf], ph[mt], vl[vf]);
                    mma16816(oacc[mt][vf], pl[mt], vh[vf]);
                }
        }
        __syncthreads();
    }

#pragma unroll
    for (int mt = 0; mt < 2; mt++)
#pragma unroll
        for (int hh = 0; hh < 2; hh++) {
            int r = wm * 32 + mt * 16 + g + hh * 8;
            float inv = 1.f / Lrow[r];
#pragma unroll
            for (int vf = 0; vf < 4; vf++) {
                int c = wn * 32 + vf * 8 + tig * 2;
                float vx = oacc[mt][vf][2 * hh] * inv;
                float vy = oacc[mt][vf][2 * hh + 1] * inv;
                half2 hi, lo;
                split2(vx, vy, hi, lo);
                size_t dst = (size_t)(qb * 64 + r) * HD + h * DHd + c;
                *(half2*)&g_oh[dst] = hi;
                *(half2*)&g_ol[dst] = lo;
            }
        }
}

// ---------------- rmsnorm variants ----------------
__global__ __launch_bounds__(256) void rmsnorm_hl_k(const float* __restrict__ in,
                                                    const float* __restrict__ w,
                                                    __half* __restrict__ ohi,
                                                    __half* __restrict__ olo, int cols) {
    int row = blockIdx.x;
    const float* r = in + (size_t)row * cols;
    float ss = 0.f;
    for (int i = threadIdx.x; i < cols; i += 256) { float v = r[i]; ss += v * v; }
    __shared__ float red[256];
    red[threadIdx.x] = ss; __syncthreads();
    for (int st = 128; st > 0; st >>= 1) {
        if (threadIdx.x < st) red[threadIdx.x] += red[threadIdx.x + st];
        __syncthreads();
    }
    float scale = rsqrtf(red[0] / (float)cols + EPSf);
    for (int i = threadIdx.x; i < cols; i += 256) {
        float val = r[i] * scale * w[i];
        __half hv = __float2half_rn(val);
        ohi[(size_t)row * cols + i] = hv;
        olo[(size_t)row * cols + i] = __float2half_rn(val - __half2float(hv));
    }
}

__global__ __launch_bounds__(256) void rmsnorm_th_k(const float* __restrict__ in,
                                                    const float* __restrict__ w,
                                                    float* __restrict__ out,
                                                    __half* __restrict__ ohi, int cols) {
    int row = blockIdx.x;
    const float* r = in + (size_t)row * cols;
    float ss = 0.f;
    for (int i = threadIdx.x; i < cols; i += 256) { float v = r[i]; ss += v * v; }
    __shared__ float red[256];
    red[threadIdx.x] = ss; __syncthreads();
    for (int st = 128; st > 0; st >>= 1) {
        if (threadIdx.x < st) red[threadIdx.x] += red[threadIdx.x + st];
        __syncthreads();
    }
    float scale = rsqrtf(red[0] / (float)cols + EPSf);
    for (int i = threadIdx.x; i < cols; i += 256) {
        float val = r[i] * scale * w[i];
        out[(size_t)row * cols + i] = val;
        ohi[(size_t)row * cols + i] = __float2half_rn(val);
    }
}

// ---------------- fused: sum K-split partials + rmsnorm + RoPE + hi/lo (y=0 q, y=1 k),
//                  y=2: v combine + hi/lo split ----------------
__global__ __launch_bounds__(256) void rms_rope_k(
    const float* __restrict__ qsrc, const float* __restrict__ qw,
    __half* __restrict__ qhi, __half* __restrict__ qlo,
    const float* __restrict__ ksrc, const float* __restrict__ kw,
    __half* __restrict__ khi, __half* __restrict__ klo,
    const float* __restrict__ vsrc,
    __half* __restrict__ vhi, __half* __restrict__ vlo)
{
    __shared__ float rowbuf[2048];
    __shared__ float red[256];
    int row = blockIdx.x;
    int sel = blockIdx.y;
    if (sel == 2) {
        const float* v0 = vsrc + (size_t)row * KVD;
        const float* v1 = vsrc + (size_t)Sq * KVD + (size_t)row * KVD;
        for (int i = threadIdx.x; i < KVD; i += 256) {
            float val = v0[i] + v1[i];
            __half hv = __float2half_rn(val);
            vhi[(size_t)row * KVD + i] = hv;
            vlo[(size_t)row * KVD + i] = __float2half_rn(val - __half2float(hv));
        }
        return;
    }
    int isk = sel;
    int cols = isk ? KVD : HD;
    float scale = isk ? 1.0f : 0.08838834764831845f;
    const float* src = isk ? ksrc : qsrc;
    const float* src2 = src + (size_t)Sq * cols;
    const float* w = isk ? kw : qw;
    __half* hi = isk ? khi : qhi;
    __half* lo = isk ? klo : qlo;
    const float* r = src + (size_t)row * cols;
    const float* r2 = src2 + (size_t)row * cols;
    float ss = 0.f;
    for (int i = threadIdx.x; i < cols; i += 256) {
        float v = r[i] + r2[i];
        rowbuf[i] = v;
        ss += v * v;
    }
    red[threadIdx.x] = ss; __syncthreads();
    for (int st = 128; st > 0; st >>= 1) {
        if (threadIdx.x < st) red[threadIdx.x] += red[threadIdx.x + st];
        __syncthreads();
    }
    float sc = rsqrtf(red[0] / (float)cols + EPSf);
    for (int i = threadIdx.x; i < cols; i += 256) {
        int d = i & 127;
        float val = rowbuf[i] * sc * w[i];
        float outv;
        if (d < 32) {
            float inv = powf(1.0e6f, -(float)d / 32.f);
            float a = (float)row * inv;
            float v2 = rowbuf[i + 32] * sc * w[i + 32];
            outv = val * cosf(a) - v2 * sinf(a);
        } else if (d < 64) {
            int p = d - 32;
            float inv = powf(1.0e6f, -(float)p / 32.f);
            float a = (float)row * inv;
            float v2 = rowbuf[i - 32] * sc * w[i - 32];
            outv = val * cosf(a) + v2 * sinf(a);
        } else {
            outv = val;
        }
        outv *= scale;
        __half hv = __float2half_rn(outv);
        hi[(size_t)row * cols + i] = hv;
        lo[(size_t)row * cols + i] = __float2half_rn(outv - __half2float(hv));
    }
}

// ---------------- router ----------------
__global__ __launch_bounds__(256) void reset_k() {
    if (threadIdx.x < En) g_cnt[threadIdx.x] = 0;
}

__global__ __launch_bounds__(256) void router_k(const float* __restrict__ Tm,
                                                const float* __restrict__ rw,
                                                const float* __restrict__ rb) {
    int row = blockIdx.x, tid = threadIdx.x;
    const float* r = Tm + (size_t)row * Dm;
    float loc[En] = {};
    for (int d = tid; d < Dm; d += 256) {
        float x = r[d];
#pragma unroll
        for (int e = 0; e < En; e++) loc[e] += x * rw[d * En + e];
    }
    __shared__ float sred[256 * En];
#pragma unroll
    for (int e = 0; e < En; e++) sred[tid * En + e] = loc[e];
    __syncthreads();
    for (int st = 128; st > 0; st >>= 1) {
        if (tid < st)
#pragma unroll
            for (int e = 0; e < En; e++) sred[tid * En + e] += sred[(tid + st) * En + e];
        __syncthreads();
    }
    if (tid == 0) {
        float sig[En], scv[En];
#pragma unroll
        for (int e = 0; e < En; e++) {
            float l = sred[e];
            sig[e] = 1.f / (1.f + expf(-l));
            scv[e] = sig[e] + rb[e];
        }
        int i0 = 0;
#pragma unroll
        for (int e = 1; e < En; e++) if (scv[e] > scv[i0]) i0 = e;
        int i1 = -1;
#pragma unroll
        for (int e = 0; e < En; e++)
            if (e != i0 && (i1 < 0 || scv[e] > scv[i1])) i1 = e;
        float a0 = sig[i0], a1 = sig[i1], s = a0 + a1;
        float w0 = a0 / s, w1 = a1 / s;
        int p = atomicAdd(&g_cnt[i0], 1);
        g_ptok[i0 * Sq + p] = row; g_pw[i0 * Sq + p] = w0; g_pslot[i0 * Sq + p] = 0;
        p = atomicAdd(&g_cnt[i1], 1);
        g_ptok[i1 * Sq + p] = row; g_pw[i1 * Sq + p] = w1; g_pslot[i1 * Sq + p] = 1;
    }
}

// ---------------- act = silu(gate)*up (half in/out) ----------------
__global__ __launch_bounds__(256) void act_k() {
    int e = blockIdx.z;
    int cnt = g_cnt[e];
    int i = (blockIdx.x * 256 + threadIdx.x) * 8;
    int row = i >> 10;
    if (row >= cnt) return;
    size_t idx = (size_t)e * Sq * Id + i;
#pragma unroll
    for (int j = 0; j < 4; j++) {
        half2 gh = *(half2*)(g_gateh + idx + 2 * j);
        half2 uh = *(half2*)(g_uph + idx + 2 * j);
        float g0 = __low2float(gh), g1 = __high2float(gh);
        float u0 = __low2float(uh), u1 = __high2float(uh);
        float a0 = (g0 / (1.f + expf(-g0))) * u0;
        float a1 = (g1 / (1.f + expf(-g1))) * u1;
        *(half2*)(g_acth + idx + 2 * j) = __floats2half2_rn(a0, a1);
    }
}

// ---------------- final: out = x1 + moe0 + moe1 (float4) ----------------
__global__ __launch_bounds__(256) void final_add_k(float* __restrict__ out) {
    int i = (blockIdx.x * 256 + threadIdx.x) * 4;
    float4 a = *(float4*)(out + i);
    float4 b = *(float4*)(g_moe + i);
    float4 c = *(float4*)(g_moe + (size_t)Sq * Dm + i);
    a.x += b.x + c.x; a.y += b.y + c.y; a.z += b.z + c.z; a.w += b.w + c.w;
    *(float4*)(out + i) = a;
}

// ---------------- host orchestration ----------------
extern "C" void kernel_launch(void* const* d_in, const int* in_sizes, int n_in,
                              void* d_out, int out_size) {
    const float* x    = (const float*)d_in[0];
    const float* ln1  = (const float*)d_in[1];
    const float* ln2  = (const float*)d_in[2];
    const float* wq   = (const float*)d_in[3];
    const float* wk   = (const float*)d_in[4];
    const float* wv   = (const float*)d_in[5];
    const float* wo   = (const float*)d_in[6];
    const float* qn   = (const float*)d_in[7];
    const float* kn   = (const float*)d_in[8];
    const float* rw   = (const float*)d_in[9];
    const float* rb   = (const float*)d_in[10];
    const float* wg   = (const float*)d_in[11];
    const float* wu   = (const float*)d_in[12];
    const float* wd   = (const float*)d_in[13];
    float* out = (float*)d_out;

    float *pq, *pk, *pv, *pt;
    cudaGetSymbolAddress((void**)&pq, g_q);
    cudaGetSymbolAddress((void**)&pk, g_k);
    cudaGetSymbolAddress((void**)&pv, g_v);
    cudaGetSymbolAddress((void**)&pt, g_t);
    __half *hh, *hl, *qh, *ql, *kh, *kl, *vh, *vl, *oh, *ol, *th, *gateh, *uph, *acth;
    cudaGetSymbolAddress((void**)&hh, g_hh);   cudaGetSymbolAddress((void**)&hl, g_hl);
    cudaGetSymbolAddress((void**)&qh, g_qh);   cudaGetSymbolAddress((void**)&ql, g_ql);
    cudaGetSymbolAddress((void**)&kh, g_kh2);  cudaGetSymbolAddress((void**)&kl, g_kl2);
    cudaGetSymbolAddress((void**)&vh, g_vh);   cudaGetSymbolAddress((void**)&vl, g_vl);
    cudaGetSymbolAddress((void**)&oh, g_oh);   cudaGetSymbolAddress((void**)&ol, g_ol);
    cudaGetSymbolAddress((void**)&th, g_th);
    cudaGetSymbolAddress((void**)&gateh, g_gateh);
    cudaGetSymbolAddress((void**)&uph, g_uph);
    cudaGetSymbolAddress((void**)&acth, g_acth);
    __half *qkvh, *qkvl, *woh, *wol, *guh, *wdh;
    cudaGetSymbolAddress((void**)&qkvh, w_qkvh); cudaGetSymbolAddress((void**)&qkvl, w_qkvl);
    cudaGetSymbolAddress((void**)&woh, w_oh);    cudaGetSymbolAddress((void**)&wol, w_ol);
    cudaGetSymbolAddress((void**)&guh, w_guh);   cudaGetSymbolAddress((void**)&wdh, w_dh);

    cudaFuncSetAttribute(attn_mma, cudaFuncAttributeMaxDynamicSharedMemorySize, ATT_SMEM);
    cudaFuncSetAttribute(gemm_mma2<false,false,true,5,2>, cudaFuncAttributeMaxDynamicSharedMemorySize, SM_SPLIT);
    cudaFuncSetAttribute(gemm_mma2<false,false,true,1,1>, cudaFuncAttributeMaxDynamicSharedMemorySize, SM_SPLIT);
    cudaFuncSetAttribute(gemm_mma2<true ,true ,false,6,1>, cudaFuncAttributeMaxDynamicSharedMemorySize, SM_SINGLE);
    cudaFuncSetAttribute(gemm_mma2<false,true ,false,4,1>, cudaFuncAttributeMaxDynamicSharedMemorySize, SM_SINGLE);

    // 0a. fork side stream: MoE weight convert overlaps the attention phase
    cudaEventRecord(g_evFork, 0);
    cudaStreamWaitEvent(g_s2, g_evFork, 0);
    conv_single_all<<<dim3(8192, 3), 256, 0, g_s2>>>(wg, wu, wd, guh, wdh);
    cudaEventRecord(g_evJoin, g_s2);

    // 0b. attention weight converts (main stream; needed by QKV)
    conv_split_all<<<dim3(2048, 4), 256>>>(wq, wk, wv, wo, qkvh, qkvl, woh, wol);

    // 1. h = rmsnorm(x, ln1) -> hi/lo halves
    rmsnorm_hl_k<<<Sq, 256>>>(x, ln1, hh, hl, Dm);
    // 2. fused QKV projection, K-split x2 (partial fp32 outputs)
    gemm_mma2<false,false,true,5,2><<<dim3(3072/128, Sq/128, 2), 256, SM_SPLIT>>>(
        hh, hl, qkvh, qkvl, pq, pk, pv, nullptr, nullptr, Sq, 3072, Dm);
    // 3+4. sum partials + rmsnorm + RoPE + split (y=0 q, y=1 k); y=2 v combine+split
    rms_rope_k<<<dim3(Sq, 3), 256>>>(pq, qn, qh, ql, pk, kn, kh, kl, pv, vh, vl);
    // 5. attention (64-row q blocks, pipelined KV)
    attn_mma<<<dim3(Sq/64, Hn), 256, ATT_SMEM>>>();
    // 6. x1 = x + o @ wo
    gemm_mma2<false,false,true,1,1><<<dim3(Dm/128, Sq/128), 256, SM_SPLIT>>>(
        oh, ol, woh, wol, out, nullptr, nullptr, nullptr, x, Sq, Dm, HD);
    // 7. t = rmsnorm(x1, ln2) -> fp32 + hi
    rmsnorm_th_k<<<Sq, 256>>>(out, ln2, pt, th, Dm);
    // 8. routing
    reset_k<<<1, 256>>>();
    router_k<<<Sq, 256>>>(pt, rw, rb);
    // join: MoE weights must be converted before the expert GEMMs
    cudaStreamWaitEvent(0, g_evJoin, 0);
    // 9. fused expert gate+up (gathered, half output)
    gemm_mma2<true,true,false,6,1><<<dim3(2048/128, Sq/128, En), 256, SM_SINGLE>>>(
        th, nullptr, guh, nullptr, gateh, uph, nullptr, nullptr, nullptr, Sq, 2048, Dm);
    // 10. act (half in/out)
    act_k<<<dim3((Sq*Id)/2048, 1, En), 256>>>();
    // 11. down GEMM + weighted scatter
    gemm_mma2<false,true,false,4,1><<<dim3(Dm/128, Sq/128, En), 256, SM_SINGLE>>>(
        acth, nullptr, wdh, nullptr, nullptr, nullptr, nullptr, nullptr, nullptr, Sq, Dm, Id);
    // 12. out = x1 + moe
    final_add_k<<<(Sq*Dm)/1024, 256>>>(out);
}

// round 15
// speedup vs baseline: 1.6241x; 1.0152x over previous
#include <cuda_runtime.h>
#include <cuda_fp16.h>
#include <math.h>
#include <stdint.h>

// ---------------- problem constants ----------------
#define Sq   2048
#define Dm   2048
#define Hn   16
#define KVn  4
#define DHd  128
#define En   8
#define Id   1024
#define HD   2048
#define KVD  512
#define EPSf 1e-6f

// ---------------- static device scratch ----------------
__device__ float g_q   [2*Sq*HD];    // two K-split partials
__device__ float g_k   [2*Sq*KVD];
__device__ float g_v   [2*Sq*KVD];
__device__ float g_t   [Sq*Dm];
__device__ float g_moe [2*Sq*Dm];
__device__ int   g_cnt [En];
__device__ int   g_ptok[En*Sq];
__device__ float g_pw  [En*Sq];
__device__ int   g_pslot[En*Sq];
// fp16 activations
__device__ __half g_hh [Sq*Dm];
__device__ __half g_hl [Sq*Dm];
__device__ __half g_qh [Sq*HD];
__device__ __half g_ql [Sq*HD];
__device__ __half g_kh2[Sq*KVD];
__device__ __half g_kl2[Sq*KVD];
__device__ __half g_vh [Sq*KVD];
__device__ __half g_vl [Sq*KVD];
__device__ __half g_oh [Sq*HD];
__device__ __half g_ol [Sq*HD];
__device__ __half g_th [Sq*Dm];
__device__ __half g_gateh[En*Sq*Id];
__device__ __half g_uph  [En*Sq*Id];
__device__ __half g_acth [En*Sq*Id];
// fp16 weights (qkv concatenated: cols 0-2047 q, 2048-2559 k, 2560-3071 v)
__device__ __half w_qkvh[Dm*3072];
__device__ __half w_qkvl[Dm*3072];
__device__ __half w_oh[HD*Dm];
__device__ __half w_ol[HD*Dm];
__device__ __half w_guh[En*Dm*2048];   // cols 0-1023 gate, 1024-2047 up
__device__ __half w_dh [En*Id*Dm];

// ---------------- side stream for convert overlap (host objects only) ----------------
static cudaStream_t g_s2;
static cudaEvent_t g_evFork, g_evJoin;
static struct StreamInit {
    StreamInit() {
        cudaStreamCreateWithFlags(&g_s2, cudaStreamNonBlocking);
        cudaEventCreateWithFlags(&g_evFork, cudaEventDisableTiming);
        cudaEventCreateWithFlags(&g_evJoin, cudaEventDisableTiming);
    }
} g_streamInit;

// ---------------- helpers ----------------
__device__ __forceinline__ uint32_t smem_u32(const void* p) {
    uint32_t a;
    asm("{ .reg .u64 t; cvta.to.shared.u64 t, %1; cvt.u32.u64 %0, t; }" : "=r"(a) : "l"(p));
    return a;
}
__device__ __forceinline__ void ldsm4(uint32_t* r, uint32_t a) {
    asm volatile("ldmatrix.sync.aligned.m8n8.x4.shared.b16 {%0,%1,%2,%3}, [%4];"
                 : "=r"(r[0]), "=r"(r[1]), "=r"(r[2]), "=r"(r[3]) : "r"(a));
}
__device__ __forceinline__ void ldsm4t(uint32_t* r, uint32_t a) {
    asm volatile("ldmatrix.sync.aligned.m8n8.x4.trans.shared.b16 {%0,%1,%2,%3}, [%4];"
                 : "=r"(r[0]), "=r"(r[1]), "=r"(r[2]), "=r"(r[3]) : "r"(a));
}
__device__ __forceinline__ void mma16816(float* d, const uint32_t* a, const uint32_t* b) {
    asm volatile("mma.sync.aligned.m16n8k16.row.col.f32.f16.f16.f32 "
                 "{%0,%1,%2,%3}, {%4,%5,%6,%7}, {%8,%9}, {%0,%1,%2,%3};"
                 : "+f"(d[0]), "+f"(d[1]), "+f"(d[2]), "+f"(d[3])
                 : "r"(a[0]), "r"(a[1]), "r"(a[2]), "r"(a[3]), "r"(b[0]), "r"(b[1]));
}
__device__ __forceinline__ void split2(float x, float y, half2& hi, half2& lo) {
    hi = __floats2half2_rn(x, y);
    lo = __floats2half2_rn(x - __low2float(hi), y - __high2float(hi));
}
#define CP16(dst, src) \
    asm volatile("cp.async.cg.shared.global [%0], [%1], 16;" :: "r"((uint32_t)(dst)), "l"(src))
#define CP_COMMIT() asm volatile("cp.async.commit_group;" ::: "memory")
#define CP_WAIT(n)  asm volatile("cp.async.wait_group %0;" :: "n"(n) : "memory")

// ---------------- fused weight converts ----------------
__global__ __launch_bounds__(256) void conv_split_all(
    const float* wq, const float* wk, const float* wv, const float* wo,
    __half* qkvh, __half* qkvl, __half* woh, __half* wol)
{
    int y = blockIdx.y;
    int nblk = (y == 0 || y == 3) ? 2048 : 512;
    if (blockIdx.x >= nblk) return;
    const float* s = y == 0 ? wq : y == 1 ? wk : y == 2 ? wv : wo;
    size_t base = ((size_t)blockIdx.x * 256 + threadIdx.x) * 8;
#pragma unroll
    for (int j = 0; j < 2; j++) {
        size_t i = base + 4 * j;
        float4 v = *(const float4*)(s + i);
        half2 a0, b0, a1, b1;
        split2(v.x, v.y, a0, b0); split2(v.z, v.w, a1, b1);
        size_t d;
        __half *hi, *lo;
        if (y == 3) { d = i; hi = woh; lo = wol; }
        else if (y == 0) { size_t r = i >> 11, c = i & 2047; d = r * 3072 + c; hi = qkvh; lo = qkvl; }
        else { size_t r = i / 512, c = i % 512; d = r * 3072 + (y == 1 ? 2048 : 2560) + c; hi = qkvh; lo = qkvl; }
        *(half2*)(hi + d) = a0; *(half2*)(hi + d + 2) = a1;
        *(half2*)(lo + d) = b0; *(half2*)(lo + d + 2) = b1;
    }
}
__global__ __launch_bounds__(256) void conv_single_all(
    const float* wg, const float* wu, const float* wd,
    __half* guh, __half* wdh)
{
    int y = blockIdx.y;
    const float* s = y == 0 ? wg : y == 1 ? wu : wd;
    size_t base = ((size_t)blockIdx.x * 256 + threadIdx.x) * 8;
#pragma unroll
    for (int j = 0; j < 2; j++) {
        size_t i = base + 4 * j;
        float4 v = *(const float4*)(s + i);
        half2 h0 = __floats2half2_rn(v.x, v.y);
        half2 h1 = __floats2half2_rn(v.z, v.w);
        size_t d;
        __half* dst;
        if (y == 2) { d = i; dst = wdh; }
        else {
            size_t e = i / ((size_t)Dm * Id);
            size_t rem = i % ((size_t)Dm * Id);
            size_t r = rem >> 10, c = rem & 1023;
            d = e * (size_t)Dm * 2048 + r * 2048 + (y ? 1024 : 0) + c;
            dst = guh;
        }
        *(half2*)(dst + d) = h0; *(half2*)(dst + d + 2) = h1;
    }
}

// ================= fp16 mma GEMM: 128 threads, 4 warps, 64x64 warp tile =================
#define AT_SZ 10240     // 128 rows x 80B
#define BT_SZ 8704      // 32 rows x 272B
#define SM_SPLIT  (3 * (2*AT_SZ + 2*BT_SZ))          // 113664, no header
#define SM_SINGLE (2048 + 4 * (AT_SZ + BT_SZ))       // 77824, with header

// OMODE: 0 f32, 1 f32+res, 4 moe-scatter, 5 qkv triple (K-split partials), 6 gate/up pair
template<bool GATHER, bool EXPERT, bool SPLIT, int OMODE, int KSPLIT>
__global__ __launch_bounds__(128, 2) void gemm_mma2(
    const __half* __restrict__ Ah, const __half* __restrict__ Al,
    const __half* __restrict__ Bh, const __half* __restrict__ Bl,
    void* __restrict__ O0, void* __restrict__ O1,
    void* __restrict__ O2, void* __restrict__ O3,
    const float* __restrict__ res,
    int M, int N, int K)
{
    extern __shared__ char smem[];
    constexpr int STAGES = SPLIT ? 3 : 4;
    constexpr bool HDR = (GATHER || OMODE == 4);
    const int tid = threadIdx.x, lane = tid & 31, wid = tid >> 5;
    const int wm = wid & 1, wn = wid >> 1;          // 2m x 2n warp grid, 64x64 tiles
    const int STG  = SPLIT ? (2 * AT_SZ + 2 * BT_SZ) : (AT_SZ + BT_SZ);
    const int BOFF = SPLIT ? 2 * AT_SZ : AT_SZ;

    int e = 0, cnt = M;
    const __half* Ahe = Ah;
    const __half* Bhe = Bh;
    const __half* Ble = Bl;
    const int kz = (KSPLIT == 2) ? blockIdx.z : 0;
    const int Keff = K / KSPLIT;
    const int kbase = kz * Keff;
    if (EXPERT) {
        e = blockIdx.z;
        cnt = g_cnt[e];
        Bhe = Bh + (size_t)e * K * N;
        if (SPLIT) Ble = Bl + (size_t)e * K * N;
        if (!GATHER) Ahe = Ah + (size_t)e * Sq * K;
    }
    const int m0 = blockIdx.y * 128;
    if (EXPERT && m0 >= cnt) return;
    const int n0 = blockIdx.x * 128;

    int*   stok = (int*)smem;
    float* swt  = (float*)(smem + 512);
    int*   ssl  = (int*)(smem + 1024);
    if (HDR) {
        {
            int r = m0 + tid;
            bool ok = r < cnt;
            stok[tid] = ok ? g_ptok[e * Sq + r] : 0;
            if (OMODE == 4) {
                swt[tid] = ok ? g_pw[e * Sq + r] : 0.f;
                ssl[tid] = ok ? g_pslot[e * Sq + r] : 0;
            }
        }
        __syncthreads();
    }
    const uint32_t sb = smem_u32(smem);
    const uint32_t tb = sb + (HDR ? 2048 : 0);
    const int T = Keff / 32;

#define ISSUE(it) do { \
        int _k0 = kbase + (it) * 32; \
        uint32_t _s0 = tb + (uint32_t)((it) % STAGES) * STG; \
        _Pragma("unroll") \
        for (int _j = 0; _j < 4; _j++) { \
            int _idx = tid + _j * 128; \
            int _row = _idx >> 2, _c = _idx & 3; \
            int _gr = GATHER ? stok[_row] : (m0 + _row); \
            CP16(_s0 + _row * 80 + _c * 16, Ahe + (size_t)_gr * K + _k0 + _c * 8); \
            if (SPLIT) CP16(_s0 + AT_SZ + _row * 80 + _c * 16, Al + (size_t)_gr * K + _k0 + _c * 8); \
        } \
        _Pragma("unroll") \
        for (int _j = 0; _j < 4; _j++) { \
            int _idx = tid + _j * 128; \
            int _row = _idx >> 4, _c = _idx & 15; \
            CP16(_s0 + BOFF + _row * 272 + _c * 16, Bhe + (size_t)(_k0 + _row) * N + n0 + _c * 8); \
            if (SPLIT) CP16(_s0 + BOFF + BT_SZ + _row * 272 + _c * 16, \
                            Ble + (size_t)(_k0 + _row) * N + n0 + _c * 8); \
        } \
        CP_COMMIT(); \
    } while (0)

#pragma unroll
    for (int p = 0; p < STAGES - 1; p++) {
        if (p < T) ISSUE(p); else CP_COMMIT();
    }

    float acc[4][8][4] = {};
    for (int it = 0; it < T; ++it) {
        CP_WAIT(STAGES - 2);
        __syncthreads();
        {
            int nx = it + STAGES - 1;
            if (nx < T) ISSUE(nx); else CP_COMMIT();
        }
        uint32_t s0 = tb + (uint32_t)(it % STAGES) * STG;
#pragma unroll
        for (int ks = 0; ks < 2; ks++) {
            uint32_t ah[4][4], al[4][4], bh[8][2], bl[8][2];
            int am = wm * 64 + (lane & 7) + ((lane >> 3) & 1) * 8;
            int ak = ks * 16 + (lane >> 4) * 8;
            uint32_t ab = s0 + am * 80 + ak * 2;
#pragma unroll
            for (int mt = 0; mt < 4; mt++) {
                ldsm4(ah[mt], ab + mt * 16 * 80);
                if (SPLIT) ldsm4(al[mt], ab + AT_SZ + mt * 16 * 80);
            }
            int bk = ks * 16 + (lane & 7) + ((lane >> 3) & 1) * 8;
            int bn = wn * 64 + (lane >> 4) * 8;
            uint32_t bb = s0 + BOFF + bk * 272 + bn * 2;
#pragma unroll
            for (int t = 0; t < 4; t++) {
                uint32_t rr[4];
                ldsm4t(rr, bb + t * 32);
                bh[2 * t][0] = rr[0]; bh[2 * t][1] = rr[1];
                bh[2 * t + 1][0] = rr[2]; bh[2 * t + 1][1] = rr[3];
                if (SPLIT) {
                    ldsm4t(rr, bb + BT_SZ + t * 32);
                    bl[2 * t][0] = rr[0]; bl[2 * t][1] = rr[1];
                    bl[2 * t + 1][0] = rr[2]; bl[2 * t + 1][1] = rr[3];
                }
            }
#pragma unroll
            for (int mt = 0; mt < 4; mt++)
#pragma unroll
                for (int nt = 0; nt < 8; nt++) {
                    mma16816(acc[mt][nt], ah[mt], bh[nt]);
                    if (SPLIT) {
                        mma16816(acc[mt][nt], ah[mt], bl[nt]);
                        mma16816(acc[mt][nt], al[mt], bh[nt]);
                    }
                }
        }
    }
#undef ISSUE

    const int g = lane >> 2, tig = lane & 3;
#pragma unroll
    for (int mt = 0; mt < 4; mt++) {
#pragma unroll
        for (int hh = 0; hh < 2; hh++) {
            int row = wm * 64 + mt * 16 + g + hh * 8;
            if (EXPERT && m0 + row >= cnt) continue;
            int m = m0 + row;
            if (OMODE == 4) {
                int token = stok[row]; float w = swt[row]; int slot = ssl[row];
                float* dst = g_moe + ((size_t)slot * Sq + token) * Dm + n0;
#pragma unroll
                for (int nt = 0; nt < 8; nt++) {
                    int c = wn * 64 + nt * 8 + tig * 2;
                    *(float2*)(dst + c) =
                        make_float2(w * acc[mt][nt][2 * hh], w * acc[mt][nt][2 * hh + 1]);
                }
            } else if (OMODE == 5) {
                float* dst;
                if (n0 < HD)
                    dst = (float*)O0 + (size_t)kz * Sq * HD + (size_t)m * HD + n0;
                else if (n0 < HD + KVD)
                    dst = (float*)O1 + (size_t)kz * Sq * KVD + (size_t)m * KVD + (n0 - HD);
                else
                    dst = (float*)O2 + (size_t)kz * Sq * KVD + (size_t)m * KVD + (n0 - HD - KVD);
#pragma unroll
                for (int nt = 0; nt < 8; nt++) {
                    int c = wn * 64 + nt * 8 + tig * 2;
                    *(float2*)(dst + c) =
                        make_float2(acc[mt][nt][2 * hh], acc[mt][nt][2 * hh + 1]);
                }
            } else if (OMODE == 6) {
                __half* base = (n0 < Id) ? (__half*)O0 : (__half*)O1;
                int nloc = (n0 < Id) ? n0 : n0 - Id;
                __half* dst = base + (size_t)e * Sq * Id + (size_t)m * Id + nloc;
#pragma unroll
                for (int nt = 0; nt < 8; nt++) {
                    int c = wn * 64 + nt * 8 + tig * 2;
                    *(half2*)(dst + c) =
                        __floats2half2_rn(acc[mt][nt][2 * hh], acc[mt][nt][2 * hh + 1]);
                }
            } else {
                float* dst = (float*)O0 + (size_t)m * N + n0;
                const float* rs = (OMODE == 1) ? (res + (size_t)m * N + n0) : nullptr;
#pragma unroll
                for (int nt = 0; nt < 8; nt++) {
                    int c = wn * 64 + nt * 8 + tig * 2;
                    float2 v = make_float2(acc[mt][nt][2 * hh], acc[mt][nt][2 * hh + 1]);
                    if (OMODE == 1) { v.x += rs[c]; v.y += rs[c + 1]; }
                    *(float2*)(dst + c) = v;
                }
            }
        }
    }
}

// ================= flash attention (64-row q blocks, K/V double-buffered) =====
#define ATT_SMEM 195072
#define LDP 72

__global__ __launch_bounds__(256) void attn_mma() {
    extern __shared__ char smem[];
    const uint32_t sb = smem_u32(smem);
    const int qb = gridDim.x - 1 - blockIdx.x;
    const int h = blockIdx.y, kvh = h >> 2;
    const int tid = threadIdx.x, lane = tid & 31, wid = tid >> 5;
    const int wm = wid & 1, wn = wid >> 1;
    float* maxb = (float*)(smem + 192512);
    float* sumb = (float*)(smem + 193536);
    float* Mrow = (float*)(smem + 194560);
    float* Lrow = (float*)(smem + 194816);

#pragma unroll
    for (int j = 0; j < 8; j++) {
        int idx = tid + j * 256;
        int arr = idx >> 10, r = (idx >> 4) & 63, c = idx & 15;
        const __half* src = (arr ? g_ql : g_qh) + (size_t)(qb * 64 + r) * HD + h * DHd + c * 8;
        CP16(sb + arr * 17408 + r * 272 + c * 16, src);
    }
#pragma unroll
    for (int j = 0; j < 16; j++) {
        int idx = tid + j * 256;
        int arr = idx >> 10, r = (idx >> 4) & 63, c = idx & 15;
        const __half* s = arr == 0 ? g_kh2 : arr == 1 ? g_kl2 : arr == 2 ? g_vh : g_vl;
        CP16(sb + 34816 + arr * 17408 + r * 272 + c * 16,
             s + (size_t)r * KVD + kvh * DHd + c * 8);
    }
    CP_COMMIT();
    if (tid < 64) { Mrow[tid] = -INFINITY; Lrow[tid] = 0.f; }

    float oacc[2][4][4] = {};
    const int g = lane >> 2, tig = lane & 3;
    const int arow = wm * 32 + (lane & 7) + ((lane >> 3) & 1) * 8;
    const int brow16 = wn * 16 + (lane & 7) + 8 * (lane >> 4);

    for (int t = 0; t <= qb; t++) {
        const uint32_t B = sb + 34816 + (uint32_t)(t & 1) * 69632;
        if (t < qb) {
            uint32_t B1 = sb + 34816 + (uint32_t)((t + 1) & 1) * 69632;
#pragma unroll
            for (int j = 0; j < 16; j++) {
                int idx = tid + j * 256;
                int arr = idx >> 10, r = (idx >> 4) & 63, c = idx & 15;
                const __half* s = arr == 0 ? g_kh2 : arr == 1 ? g_kl2 : arr == 2 ? g_vh : g_vl;
                CP16(B1 + arr * 17408 + r * 272 + c * 16,
                     s + (size_t)((t + 1) * 64 + r) * KVD + kvh * DHd + c * 8);
            }
            CP_COMMIT();
            CP_WAIT(1);
        } else {
            CP_WAIT(0);
        }
        __syncthreads();

        float sacc[2][2][4] = {};
#pragma unroll
        for (int ks = 0; ks < 8; ks++) {
            uint32_t ah[2][4], al[2][4], bh[2][2], bl[2][2];
            int ak = ks * 16 + (lane >> 4) * 8;
            uint32_t ab = sb + (arow * 136 + ak) * 2;
            ldsm4(ah[0], ab);
            ldsm4(ah[1], ab + 16 * 272);
            ldsm4(al[0], ab + 17408);
            ldsm4(al[1], ab + 17408 + 16 * 272);
            int bk = ks * 16 + ((lane >> 3) & 1) * 8;
            uint32_t bb = B + (brow16 * 136 + bk) * 2;
            {
                uint32_t rr[4];
                ldsm4(rr, bb);
                bh[0][0] = rr[0]; bh[0][1] = rr[1];
                bh[1][0] = rr[2]; bh[1][1] = rr[3];
                ldsm4(rr, bb + 17408);
                bl[0][0] = rr[0]; bl[0][1] = rr[1];
                bl[1][0] = rr[2]; bl[1][1] = rr[3];
            }
#pragma unroll
            for (int mt = 0; mt < 2; mt++)
#pragma unroll
                for (int nf = 0; nf < 2; nf++) {
                    mma16816(sacc[mt][nf], ah[mt], bh[nf]);
                    mma16816(sacc[mt][nf], ah[mt], bl[nf]);
                    mma16816(sacc[mt][nf], al[mt], bh[nf]);
                }
        }

        if (t == qb) {
#pragma unroll
            for (int mt = 0; mt < 2; mt++)
#pragma unroll
                for (int nf = 0; nf < 2; nf++)
#pragma unroll
                    for (int i = 0; i < 4; i++) {
                        int row = wm * 32 + mt * 16 + g + (i >= 2 ? 8 : 0);
                        int col = wn * 16 + nf * 8 + tig * 2 + (i & 1);
                        if (col > row) sacc[mt][nf][i] = -INFINITY;
                    }
        }

        float rmax[2][2];
#pragma unroll
        for (int mt = 0; mt < 2; mt++)
#pragma unroll
            for (int hh = 0; hh < 2; hh++) {
                float m = fmaxf(fmaxf(sacc[mt][0][2 * hh], sacc[mt][0][2 * hh + 1]),
                                fmaxf(sacc[mt][1][2 * hh], sacc[mt][1][2 * hh + 1]));
                m = fmaxf(m, __shfl_xor_sync(0xffffffffu, m, 1));
                m = fmaxf(m, __shfl_xor_sync(0xffffffffu, m, 2));
                rmax[mt][hh] = m;
            }
        if (tig == 0) {
#pragma unroll
            for (int mt = 0; mt < 2; mt++) {
                int r = wm * 32 + mt * 16 + g;
                maxb[wn * 64 + r] = rmax[mt][0];
                maxb[wn * 64 + r + 8] = rmax[mt][1];
            }
        }
        __syncthreads();

        float alpha[2][2], mnew[2][2], rsum[2][2];
#pragma unroll
        for (int mt = 0; mt < 2; mt++)
#pragma unroll
            for (int hh = 0; hh < 2; hh++) {
                int r = wm * 32 + mt * 16 + g + hh * 8;
                float mo = Mrow[r];
                float mn = fmaxf(fmaxf(mo, maxb[r]),
                                 fmaxf(fmaxf(maxb[64 + r], maxb[128 + r]), maxb[192 + r]));
                mnew[mt][hh] = mn;
                alpha[mt][hh] = expf(mo - mn);
                rsum[mt][hh] = 0.f;
            }
#pragma unroll
        for (int mt = 0; mt < 2; mt++)
#pragma unroll
            for (int nf = 0; nf < 2; nf++)
#pragma unroll
                for (int hh = 0; hh < 2; hh++) {
                    float p0 = expf(sacc[mt][nf][2 * hh]     - mnew[mt][hh]);
                    float p1 = expf(sacc[mt][nf][2 * hh + 1] - mnew[mt][hh]);
                    rsum[mt][hh] += p0 + p1;
                    half2 hi, lo;
                    split2(p0, p1, hi, lo);
                    int r = wm * 32 + mt * 16 + g + hh * 8;
                    int c = wn * 16 + nf * 8 + tig * 2;
                    *(half2*)(smem + 174080 + (r * LDP + c) * 2) = hi;
                    *(half2*)(smem + 183296 + (r * LDP + c) * 2) = lo;
                }
#pragma unroll
        for (int mt = 0; mt < 2; mt++)
#pragma unroll
            for (int hh = 0; hh < 2; hh++) {
                float s = rsum[mt][hh];
                s += __shfl_xor_sync(0xffffffffu, s, 1);
                s += __shfl_xor_sync(0xffffffffu, s, 2);
                rsum[mt][hh] = s;
            }
        if (tig == 0) {
#pragma unroll
            for (int mt = 0; mt < 2; mt++) {
                int r = wm * 32 + mt * 16 + g;
                sumb[wn * 64 + r] = rsum[mt][0];
                sumb[wn * 64 + r + 8] = rsum[mt][1];
            }
        }
#pragma unroll
        for (int mt = 0; mt < 2; mt++)
#pragma unroll
            for (int vf = 0; vf < 4; vf++) {
                oacc[mt][vf][0] *= alpha[mt][0]; oacc[mt][vf][1] *= alpha[mt][0];
                oacc[mt][vf][2] *= alpha[mt][1]; oacc[mt][vf][3] *= alpha[mt][1];
            }
        __syncthreads();

        if (wn == 0 && tig == 0) {
#pragma unroll
            for (int mt = 0; mt < 2; mt++)
#pragma unroll
                for (int hh = 0; hh < 2; hh++) {
                    int r = wm * 32 + mt * 16 + g + hh * 8;
                    Lrow[r] = Lrow[r] * alpha[mt][hh]
                              + sumb[r] + sumb[64 + r] + sumb[128 + r] + sumb[192 + r];
                    Mrow[r] = mnew[mt][hh];
                }
        }

#pragma unroll
        for (int ks = 0; ks < 4; ks++) {
            uint32_t ph[2][4], pl[2][4], vh[4][2], vl[4][2];
            int ak = ks * 16 + (lane >> 4) * 8;
            uint32_t ab = sb + 174080 + (arow * LDP + ak) * 2;
            ldsm4(ph[0], ab);
            ldsm4(ph[1], ab + 16 * 144);
            ldsm4(pl[0], ab + 9216);
            ldsm4(pl[1], ab + 9216 + 16 * 144);
            int vk = ks * 16 + (lane & 7) + ((lane >> 3) & 1) * 8;
            int vn = wn * 32 + (lane >> 4) * 8;
            uint32_t vb = B + 34816 + (vk * 136 + vn) * 2;
#pragma unroll
            for (int ntp = 0; ntp < 2; ntp++) {
                uint32_t rr[4];
                ldsm4t(rr, vb + ntp * 32);
                vh[2 * ntp][0] = rr[0]; vh[2 * ntp][1] = rr[1];
                vh[2 * ntp + 1][0] = rr[2]; vh[2 * ntp + 1][1] = rr[3];
                ldsm4t(rr, vb + 17408 + ntp * 32);
                vl[2 * ntp][0] = rr[0]; vl[2 * ntp][1] = rr[1];
                vl[2 * ntp + 1][0] = rr[2]; vl[2 * ntp + 1][1] = rr[3];
            }
#pragma unroll
            for (int mt = 0; mt < 2; mt++)
#pragma unroll
                for (int vf = 0; vf < 4; vf++) {
                    mma16816(oacc[mt][vf], ph[mt], vh[vf]);
                    mma16816(oacc[mt][vf], ph[mt], vl[vf]);
                    mma16816(oacc[mt][vf], pl[mt], vh[vf]);
                }
        }
        __syncthreads();
    }

#pragma unroll
    for (int mt = 0; mt < 2; mt++)
#pragma unroll
        for (int hh = 0; hh < 2; hh++) {
            int r = wm * 32 + mt * 16 + g + hh * 8;
            float inv = 1.f / Lrow[r];
#pragma unroll
            for (int vf = 0; vf < 4; vf++) {
                int c = wn * 32 + vf * 8 + tig * 2;
                float vx = oacc[mt][vf][2 * hh] * inv;
                float vy = oacc[mt][vf][2 * hh + 1] * inv;
                half2 hi, lo;
                split2(vx, vy, hi, lo);
                size_t dst = (size_t)(qb * 64 + r) * HD + h * DHd + c;
                *(half2*)&g_oh[dst] = hi;
                *(half2*)&g_ol[dst] = lo;
            }
        }
}

// ---------------- rmsnorm variants ----------------
__global__ __launch_bounds__(256) void rmsnorm_hl_k(const float* __restrict__ in,
                                                    const float* __restrict__ w,
                                                    __half* __restrict__ ohi,
                                                    __half* __restrict__ olo, int cols) {
    int row = blockIdx.x;
    const float* r = in + (size_t)row * cols;
    float ss = 0.f;
    for (int i = threadIdx.x; i < cols; i += 256) { float v = r[i]; ss += v * v; }
    __shared__ float red[256];
    red[threadIdx.x] = ss; __syncthreads();
    for (int st = 128; st > 0; st >>= 1) {
        if (threadIdx.x < st) red[threadIdx.x] += red[threadIdx.x + st];
        __syncthreads();
    }
    float scale = rsqrtf(red[0] / (float)cols + EPSf);
    for (int i = threadIdx.x; i < cols; i += 256) {
        float val = r[i] * scale * w[i];
        __half hv = __float2half_rn(val);
        ohi[(size_t)row * cols + i] = hv;
        olo[(size_t)row * cols + i] = __float2half_rn(val - __half2float(hv));
    }
}

__global__ __launch_bounds__(256) void rmsnorm_th_k(const float* __restrict__ in,
                                                    const float* __restrict__ w,
                                                    float* __restrict__ out,
                                                    __half* __restrict__ ohi, int cols) {
    int row = blockIdx.x;
    const float* r = in + (size_t)row * cols;
    float ss = 0.f;
    for (int i = threadIdx.x; i < cols; i += 256) { float v = r[i]; ss += v * v; }
    __shared__ float red[256];
    red[threadIdx.x] = ss; __syncthreads();
    for (int st = 128; st > 0; st >>= 1) {
        if (threadIdx.x < st) red[threadIdx.x] += red[threadIdx.x + st];
        __syncthreads();
    }
    float scale = rsqrtf(red[0] / (float)cols + EPSf);
    for (int i = threadIdx.x; i < cols; i += 256) {
        float val = r[i] * scale * w[i];
        out[(size_t)row * cols + i] = val;
        ohi[(size_t)row * cols + i] = __float2half_rn(val);
    }
}

// ---------------- fused: sum K-split partials + rmsnorm + RoPE + hi/lo ----------------
__global__ __launch_bounds__(256) void rms_rope_k(
    const float* __restrict__ qsrc, const float* __restrict__ qw,
    __half* __restrict__ qhi, __half* __restrict__ qlo,
    const float* __restrict__ ksrc, const float* __restrict__ kw,
    __half* __restrict__ khi, __half* __restrict__ klo,
    const float* __restrict__ vsrc,
    __half* __restrict__ vhi, __half* __restrict__ vlo)
{
    __shared__ float rowbuf[2048];
    __shared__ float red[256];
    int row = blockIdx.x;
    int sel = blockIdx.y;
    if (sel == 2) {
        const float* v0 = vsrc + (size_t)row * KVD;
        const float* v1 = vsrc + (size_t)Sq * KVD + (size_t)row * KVD;
        for (int i = threadIdx.x; i < KVD; i += 256) {
            float val = v0[i] + v1[i];
            __half hv = __float2half_rn(val);
            vhi[(size_t)row * KVD + i] = hv;
            vlo[(size_t)row * KVD + i] = __float2half_rn(val - __half2float(hv));
        }
        return;
    }
    int isk = sel;
    int cols = isk ? KVD : HD;
    float scale = isk ? 1.0f : 0.08838834764831845f;
    const float* src = isk ? ksrc : qsrc;
    const float* src2 = src + (size_t)Sq * cols;
    const float* w = isk ? kw : qw;
    __half* hi = isk ? khi : qhi;
    __half* lo = isk ? klo : qlo;
    const float* r = src + (size_t)row * cols;
    const float* r2 = src2 + (size_t)row * cols;
    float ss = 0.f;
    for (int i = threadIdx.x; i < cols; i += 256) {
        float v = r[i] + r2[i];
        rowbuf[i] = v;
        ss += v * v;
    }
    red[threadIdx.x] = ss; __syncthreads();
    for (int st = 128; st > 0; st >>= 1) {
        if (threadIdx.x < st) red[threadIdx.x] += red[threadIdx.x + st];
        __syncthreads();
    }
    float sc = rsqrtf(red[0] / (float)cols + EPSf);
    for (int i = threadIdx.x; i < cols; i += 256) {
        int d = i & 127;
        float val = rowbuf[i] * sc * w[i];
        float outv;
        if (d < 32) {
            float inv = powf(1.0e6f, -(float)d / 32.f);
            float a = (float)row * inv;
            float v2 = rowbuf[i + 32] * sc * w[i + 32];
            outv = val * cosf(a) - v2 * sinf(a);
        } else if (d < 64) {
            int p = d - 32;
            float inv = powf(1.0e6f, -(float)p / 32.f);
            float a = (float)row * inv;
            float v2 = rowbuf[i - 32] * sc * w[i - 32];
            outv = val * cosf(a) + v2 * sinf(a);
        } else {
            outv = val;
        }
        outv *= scale;
        __half hv = __float2half_rn(outv);
        hi[(size_t)row * cols + i] = hv;
        lo[(size_t)row * cols + i] = __float2half_rn(outv - __half2float(hv));
    }
}

// ---------------- router ----------------
__global__ __launch_bounds__(256) void reset_k() {
    if (threadIdx.x < En) g_cnt[threadIdx.x] = 0;
}

__global__ __launch_bounds__(256) void router_k(const float* __restrict__ Tm,
                                                const float* __restrict__ rw,
                                                const float* __restrict__ rb) {
    int row = blockIdx.x, tid = threadIdx.x;
    const float* r = Tm + (size_t)row * Dm;
    float loc[En] = {};
    for (int d = tid; d < Dm; d += 256) {
        float x = r[d];
#pragma unroll
        for (int e = 0; e < En; e++) loc[e] += x * rw[d * En + e];
    }
    __shared__ float sred[256 * En];
#pragma unroll
    for (int e = 0; e < En; e++) sred[tid * En + e] = loc[e];
    __syncthreads();
    for (int st = 128; st > 0; st >>= 1) {
        if (tid < st)
#pragma unroll
            for (int e = 0; e < En; e++) sred[tid * En + e] += sred[(tid + st) * En + e];
        __syncthreads();
    }
    if (tid == 0) {
        float sig[En], scv[En];
#pragma unroll
        for (int e = 0; e < En; e++) {
            float l = sred[e];
            sig[e] = 1.f / (1.f + expf(-l));
            scv[e] = sig[e] + rb[e];
        }
        int i0 = 0;
#pragma unroll
        for (int e = 1; e < En; e++) if (scv[e] > scv[i0]) i0 = e;
        int i1 = -1;
#pragma unroll
        for (int e = 0; e < En; e++)
            if (e != i0 && (i1 < 0 || scv[e] > scv[i1])) i1 = e;
        float a0 = sig[i0], a1 = sig[i1], s = a0 + a1;
        float w0 = a0 / s, w1 = a1 / s;
        int p = atomicAdd(&g_cnt[i0], 1);
        g_ptok[i0 * Sq + p] = row; g_pw[i0 * Sq + p] = w0; g_pslot[i0 * Sq + p] = 0;
        p = atomicAdd(&g_cnt[i1], 1);
        g_ptok[i1 * Sq + p] = row; g_pw[i1 * Sq + p] = w1; g_pslot[i1 * Sq + p] = 1;
    }
}

// ---------------- act = silu(gate)*up (half in/out) ----------------
__global__ __launch_bounds__(256) void act_k() {
    int e = blockIdx.z;
    int cnt = g_cnt[e];
    int i = (blockIdx.x * 256 + threadIdx.x) * 8;
    int row = i >> 10;
    if (row >= cnt) return;
    size_t idx = (size_t)e * Sq * Id + i;
#pragma unroll
    for (int j = 0; j < 4; j++) {
        half2 gh = *(half2*)(g_gateh + idx + 2 * j);
        half2 uh = *(half2*)(g_uph + idx + 2 * j);
        float g0 = __low2float(gh), g1 = __high2float(gh);
        float u0 = __low2float(uh), u1 = __high2float(uh);
        float a0 = (g0 / (1.f + expf(-g0))) * u0;
        float a1 = (g1 / (1.f + expf(-g1))) * u1;
        *(half2*)(g_acth + idx + 2 * j) = __floats2half2_rn(a0, a1);
    }
}

// ---------------- final: out = x1 + moe0 + moe1 (float4) ----------------
__global__ __launch_bounds__(256) void final_add_k(float* __restrict__ out) {
    int i = (blockIdx.x * 256 + threadIdx.x) * 4;
    float4 a = *(float4*)(out + i);
    float4 b = *(float4*)(g_moe + i);
    float4 c = *(float4*)(g_moe + (size_t)Sq * Dm + i);
    a.x += b.x + c.x; a.y += b.y + c.y; a.z += b.z + c.z; a.w += b.w + c.w;
    *(float4*)(out + i) = a;
}

// ---------------- host orchestration ----------------
extern "C" void kernel_launch(void* const* d_in, const int* in_sizes, int n_in,
                              void* d_out, int out_size) {
    const float* x    = (const float*)d_in[0];
    const float* ln1  = (const float*)d_in[1];
    const float* ln2  = (const float*)d_in[2];
    const float* wq   = (const float*)d_in[3];
    const float* wk   = (const float*)d_in[4];
    const float* wv   = (const float*)d_in[5];
    const float* wo   = (const float*)d_in[6];
    const float* qn   = (const float*)d_in[7];
    const float* kn   = (const float*)d_in[8];
    const float* rw   = (const float*)d_in[9];
    const float* rb   = (const float*)d_in[10];
    const float* wg   = (const float*)d_in[11];
    const float* wu   = (const float*)d_in[12];
    const float* wd   = (const float*)d_in[13];
    float* out = (float*)d_out;

    float *pq, *pk, *pv, *pt;
    cudaGetSymbolAddress((void**)&pq, g_q);
    cudaGetSymbolAddress((void**)&pk, g_k);
    cudaGetSymbolAddress((void**)&pv, g_v);
    cudaGetSymbolAddress((void**)&pt, g_t);
    __half *hh, *hl, *qh, *ql, *kh, *kl, *vh, *vl, *oh, *ol, *th, *gateh, *uph, *acth;
    cudaGetSymbolAddress((void**)&hh, g_hh);   cudaGetSymbolAddress((void**)&hl, g_hl);
    cudaGetSymbolAddress((void**)&qh, g_qh);   cudaGetSymbolAddress((void**)&ql, g_ql);
    cudaGetSymbolAddress((void**)&kh, g_kh2);  cudaGetSymbolAddress((void**)&kl, g_kl2);
    cudaGetSymbolAddress((void**)&vh, g_vh);   cudaGetSymbolAddress((void**)&vl, g_vl);
    cudaGetSymbolAddress((void**)&oh, g_oh);   cudaGetSymbolAddress((void**)&ol, g_ol);
    cudaGetSymbolAddress((void**)&th, g_th);
    cudaGetSymbolAddress((void**)&gateh, g_gateh);
    cudaGetSymbolAddress((void**)&uph, g_uph);
    cudaGetSymbolAddress((void**)&acth, g_acth);
    __half *qkvh, *qkvl, *woh, *wol, *guh, *wdh;
    cudaGetSymbolAddress((void**)&qkvh, w_qkvh); cudaGetSymbolAddress((void**)&qkvl, w_qkvl);
    cudaGetSymbolAddress((void**)&woh, w_oh);    cudaGetSymbolAddress((void**)&wol, w_ol);
    cudaGetSymbolAddress((void**)&guh, w_guh);   cudaGetSymbolAddress((void**)&wdh, w_dh);

    cudaFuncSetAttribute(attn_mma, cudaFuncAttributeMaxDynamicSharedMemorySize, ATT_SMEM);
    cudaFuncSetAttribute(gemm_mma2<false,false,true,5,2>, cudaFuncAttributeMaxDynamicSharedMemorySize, SM_SPLIT);
    cudaFuncSetAttribute(gemm_mma2<false,false,true,1,1>, cudaFuncAttributeMaxDynamicSharedMemorySize, SM_SPLIT);
    cudaFuncSetAttribute(gemm_mma2<true ,true ,false,6,1>, cudaFuncAttributeMaxDynamicSharedMemorySize, SM_SINGLE);
    cudaFuncSetAttribute(gemm_mma2<false,true ,false,4,1>, cudaFuncAttributeMaxDynamicSharedMemorySize, SM_SINGLE);

    // 0a. fork side stream: MoE weight convert overlaps the attention phase
    cudaEventRecord(g_evFork, 0);
    cudaStreamWaitEvent(g_s2, g_evFork, 0);
    conv_single_all<<<dim3(8192, 3), 256, 0, g_s2>>>(wg, wu, wd, guh, wdh);
    cudaEventRecord(g_evJoin, g_s2);

    // 0b. attention weight converts
    conv_split_all<<<dim3(2048, 4), 256>>>(wq, wk, wv, wo, qkvh, qkvl, woh, wol);

    // 1. h = rmsnorm(x, ln1) -> hi/lo halves
    rmsnorm_hl_k<<<Sq, 256>>>(x, ln1, hh, hl, Dm);
    // 2. fused QKV projection, K-split x2 (partial fp32 outputs)
    gemm_mma2<false,false,true,5,2><<<dim3(3072/128, Sq/128, 2), 128, SM_SPLIT>>>(
        hh, hl, qkvh, qkvl, pq, pk, pv, nullptr, nullptr, Sq, 3072, Dm);
    // 3+4. sum partials + rmsnorm + RoPE + split (y=0 q, y=1 k); y=2 v combine+split
    rms_rope_k<<<dim3(Sq, 3), 256>>>(pq, qn, qh, ql, pk, kn, kh, kl, pv, vh, vl);
    // 5. attention (64-row q blocks, pipelined KV)
    attn_mma<<<dim3(Sq/64, Hn), 256, ATT_SMEM>>>();
    // 6. x1 = x + o @ wo
    gemm_mma2<false,false,true,1,1><<<dim3(Dm/128, Sq/128), 128, SM_SPLIT>>>(
        oh, ol, woh, wol, out, nullptr, nullptr, nullptr, x, Sq, Dm, HD);
    // 7. t = rmsnorm(x1, ln2) -> fp32 + hi
    rmsnorm_th_k<<<Sq, 256>>>(out, ln2, pt, th, Dm);
    // 8. routing
    reset_k<<<1, 256>>>();
    router_k<<<Sq, 256>>>(pt, rw, rb);
    // join: MoE weights converted before expert GEMMs
    cudaStreamWaitEvent(0, g_evJoin, 0);
    // 9. fused expert gate+up (gathered, half output)
    gemm_mma2<true,true,false,6,1><<<dim3(2048/128, Sq/128, En), 128, SM_SINGLE>>>(
        th, nullptr, guh, nullptr, gateh, uph, nullptr, nullptr, nullptr, Sq, 2048, Dm);
    // 10. act (half in/out)
    act_k<<<dim3((Sq*Id)/2048, 1, En), 256>>>();
    // 11. down GEMM + weighted scatter
    gemm_mma2<false,true,false,4,1><<<dim3(Dm/128, Sq/128, En), 128, SM_SINGLE>>>(
        acth, nullptr, wdh, nullptr, nullptr, nullptr, nullptr, nullptr, nullptr, Sq, Dm, Id);
    // 12. out = x1 + moe
    final_add_k<<<(Sq*Dm)/1024, 256>>>(out);
}